// round 1
// baseline (speedup 1.0000x reference)
#include <cuda_runtime.h>

#define Bb   2
#define Cc   512
#define Nn   2304          // 48*48
#define Gg   32
#define CG   16            // Cc/Gg
#define NH   8
#define DH   64
#define HID  512
#define QKVJ 1536
#define NKV  4
#define Ltot 2308          // Nn + NKV
#define Lpad 2368          // 37*64
#define SCALE 0.125f       // DH^-0.5

// ------------------------- scratch (device globals) -------------------------
__device__ float d_s1[Bb*Cc], d_b1[Bb*Cc], d_s2[Bb*Cc], d_b2[Bb*Cc];
__device__ float d_weff[(size_t)Bb*QKVJ*Cc];
__device__ float d_biasq[Bb*QKVJ];
__device__ float d_q[(size_t)Bb*NH*Nn*DH];
__device__ float d_k[(size_t)Bb*NH*Lpad*DH];
__device__ float d_v[(size_t)Bb*NH*Lpad*DH];
__device__ float d_ob[(size_t)Bb*Nn*HID];
__device__ float d_y[(size_t)Bb*Cc*Nn];

// ------------------------- GroupNorm stats -> affine -------------------------
// One block per (b,g). Computes mean/var over (16 channels x N tokens), emits
// per-channel effective scale/bias:  t = src*s + b
__global__ void gn_stats_kernel(const float* __restrict__ src,
                                const float* __restrict__ w,
                                const float* __restrict__ bgn,
                                float* __restrict__ sout,
                                float* __restrict__ bout) {
    int b = blockIdx.x >> 5;
    int g = blockIdx.x & 31;
    const float* p = src + ((size_t)b*Cc + g*CG) * Nn;
    float sum = 0.f, sq = 0.f;
    for (int i = threadIdx.x; i < CG*Nn; i += 256) {
        float v = p[i]; sum += v; sq += v*v;
    }
    __shared__ float r0[8], r1[8];
    __shared__ float smu, srs;
    int lane = threadIdx.x & 31, wid = threadIdx.x >> 5;
#pragma unroll
    for (int off = 16; off; off >>= 1) {
        sum += __shfl_xor_sync(~0u, sum, off);
        sq  += __shfl_xor_sync(~0u, sq,  off);
    }
    if (!lane) { r0[wid] = sum; r1[wid] = sq; }
    __syncthreads();
    if (threadIdx.x == 0) {
        float s = 0.f, q = 0.f;
#pragma unroll
        for (int i = 0; i < 8; i++) { s += r0[i]; q += r1[i]; }
        float inv = 1.f / (float)(CG*Nn);
        float mu  = s * inv;
        float var = q * inv - mu*mu;
        smu = mu; srs = rsqrtf(var + 1e-5f);
    }
    __syncthreads();
    if (threadIdx.x < CG) {
        int c = g*CG + threadIdx.x;
        float ww = w[c];
        float sc = srs * ww;
        sout[b*Cc + c] = sc;
        bout[b*Cc + c] = bgn[c] - smu * sc;
    }
}

// ------------------------- fold GN1 affine into W_qkv -------------------------
__global__ void build_weff_kernel(const float* __restrict__ wqkv) {
    int j = blockIdx.x, b = blockIdx.y;
    const float* wr = wqkv + (size_t)j*Cc;
    const float* s  = d_s1 + b*Cc;
    const float* bb = d_b1 + b*Cc;
    float* dst = d_weff + ((size_t)b*QKVJ + j)*Cc;
    float part = 0.f;
    for (int c = threadIdx.x; c < Cc; c += 128) {
        float w = wr[c];
        dst[c] = w * s[c];
        part += w * bb[c];
    }
#pragma unroll
    for (int off = 16; off; off >>= 1) part += __shfl_xor_sync(~0u, part, off);
    __shared__ float r[4];
    if (!(threadIdx.x & 31)) r[threadIdx.x >> 5] = part;
    __syncthreads();
    if (!threadIdx.x) d_biasq[b*QKVJ + j] = r[0]+r[1]+r[2]+r[3];
}

// ------------------------- memory kv prepend + zero pad -------------------------
__global__ void fill_memkv_kernel(const float* __restrict__ mem) {
    int h = blockIdx.x & 7, b = blockIdx.x >> 3;
    float* kdst = d_k + (size_t)(b*NH + h)*Lpad*DH;
    float* vdst = d_v + (size_t)(b*NH + h)*Lpad*DH;
    int t = threadIdx.x;            // 256 threads == NKV*DH
    {
        int l = t >> 6, d = t & 63;
        kdst[l*DH + d] = mem[((size_t)h*DH + d)*NKV + l];
        vdst[l*DH + d] = mem[((size_t)(NH + h)*DH + d)*NKV + l];
    }
    for (int i = t; i < (Lpad - Ltot)*DH; i += 256) {
        kdst[Ltot*DH + i] = 0.f;
        vdst[Ltot*DH + i] = 0.f;
    }
}

// ------------------------- QKV GEMM (128x128x16, 8x8/thread) -------------------------
// qkv[n][j] = sum_c x[b][c][n] * weff[b][j][c] + biasq[b][j]; scatter into q/k/v head layouts
__global__ __launch_bounds__(256) void qkv_gemm_kernel(const float* __restrict__ x) {
    int b  = blockIdx.z;
    int m0 = blockIdx.x * 128;       // token
    int n0 = blockIdx.y * 128;       // output feature j
    const float* A  = x + (size_t)b*Cc*Nn;            // A[k][m], m contiguous
    const float* Bw = d_weff + (size_t)b*QKVJ*Cc;     // Bw[j][k], k contiguous
    __shared__ __align__(16) float As[16][128];
    __shared__ __align__(16) float Bs[16][132];
    int tid = threadIdx.x;
    int ty = tid >> 4, tx = tid & 15;
    float acc[8][8];
#pragma unroll
    for (int i = 0; i < 8; i++)
#pragma unroll
        for (int j = 0; j < 8; j++) acc[i][j] = 0.f;

    for (int k0 = 0; k0 < Cc; k0 += 16) {
#pragma unroll
        for (int i = 0; i < 2; i++) {
            int idx = tid + i*256;
            int kk = idx >> 5, mm = (idx & 31) << 2;
            *(float4*)&As[kk][mm] = *(const float4*)(A + (size_t)(k0+kk)*Nn + m0 + mm);
        }
#pragma unroll
        for (int i = 0; i < 2; i++) {
            int idx = tid + i*256;
            int j = idx >> 2, kk = (idx & 3) << 2;
            float4 v = *(const float4*)(Bw + (size_t)(n0+j)*Cc + k0 + kk);
            Bs[kk+0][j] = v.x; Bs[kk+1][j] = v.y; Bs[kk+2][j] = v.z; Bs[kk+3][j] = v.w;
        }
        __syncthreads();
#pragma unroll
        for (int kk = 0; kk < 16; kk++) {
            float a[8], bb[8];
            *(float4*)a     = *(const float4*)&As[kk][ty*8];
            *(float4*)(a+4) = *(const float4*)&As[kk][ty*8+4];
            *(float4*)bb     = *(const float4*)&Bs[kk][tx*8];
            *(float4*)(bb+4) = *(const float4*)&Bs[kk][tx*8+4];
#pragma unroll
            for (int i = 0; i < 8; i++)
#pragma unroll
                for (int j = 0; j < 8; j++) acc[i][j] += a[i]*bb[j];
        }
        __syncthreads();
    }
    // epilogue: all 8 output features of this thread share (section, head)
    int jg0 = n0 + tx*8;
    int sec = jg0 >> 9;
    int jl  = jg0 & 511;
    int hh  = jl >> 6;
    int dd  = jl & 63;
    float bias[8];
#pragma unroll
    for (int j = 0; j < 8; j++) bias[j] = d_biasq[b*QKVJ + jg0 + j];
    float* base;
    if (sec == 0) base = d_q + (size_t)(b*NH + hh)*Nn*DH + dd;
    else {
        float* arr = (sec == 1) ? d_k : d_v;
        base = arr + (size_t)(b*NH + hh)*Lpad*DH + (size_t)NKV*DH + dd;
    }
#pragma unroll
    for (int i = 0; i < 8; i++) {
        int n = m0 + ty*8 + i;
        float* dst = base + (size_t)n*DH;
        float4 v0, v1;
        v0.x = acc[i][0]+bias[0]; v0.y = acc[i][1]+bias[1];
        v0.z = acc[i][2]+bias[2]; v0.w = acc[i][3]+bias[3];
        v1.x = acc[i][4]+bias[4]; v1.y = acc[i][5]+bias[5];
        v1.z = acc[i][6]+bias[6]; v1.w = acc[i][7]+bias[7];
        *(float4*)dst = v0;
        *(float4*)(dst+4) = v1;
    }
}

// ------------------------- Flash attention (64q x 64k tiles) -------------------------
__global__ __launch_bounds__(256) void flash_kernel() {
    extern __shared__ __align__(16) float sm[];
    float* Qs = sm;                   // 64 x 68
    float* Ks = sm + 64*68;
    float* Vs = sm + 2*64*68;
    float* Ps = sm + 3*64*68;
    int qt = blockIdx.x, h = blockIdx.y, b = blockIdx.z;
    int tid = threadIdx.x, ty = tid >> 4, tx = tid & 15;
    const float* qptr  = d_q + ((size_t)(b*NH + h)*Nn + qt*64)*DH;
    const float* kbase = d_k + (size_t)(b*NH + h)*Lpad*DH;
    const float* vbase = d_v + (size_t)(b*NH + h)*Lpad*DH;

#pragma unroll
    for (int i = 0; i < 4; i++) {
        int idx = tid + i*256;
        int r = idx >> 4, c4 = (idx & 15) << 2;
        float4 v = *(const float4*)(qptr + r*DH + c4);
        v.x *= SCALE; v.y *= SCALE; v.z *= SCALE; v.w *= SCALE;
        *(float4*)&Qs[r*68 + c4] = v;
    }

    float m[4], l[4], o[4][4];
#pragma unroll
    for (int i = 0; i < 4; i++) {
        m[i] = -1e30f; l[i] = 0.f;
#pragma unroll
        for (int j = 0; j < 4; j++) o[i][j] = 0.f;
    }

    for (int kt = 0; kt < 37; kt++) {
        const float* kp = kbase + (size_t)kt*64*DH;
        const float* vp = vbase + (size_t)kt*64*DH;
#pragma unroll
        for (int i = 0; i < 4; i++) {
            int idx = tid + i*256;
            int r = idx >> 4, c4 = (idx & 15) << 2;
            *(float4*)&Ks[r*68 + c4] = *(const float4*)(kp + r*DH + c4);
            *(float4*)&Vs[r*68 + c4] = *(const float4*)(vp + r*DH + c4);
        }
        __syncthreads();

        float s[4][4];
#pragma unroll
        for (int i = 0; i < 4; i++)
#pragma unroll
            for (int j = 0; j < 4; j++) s[i][j] = 0.f;
#pragma unroll
        for (int k = 0; k < 64; k += 4) {
            float4 qv[4], kv[4];
#pragma unroll
            for (int i = 0; i < 4; i++) qv[i] = *(const float4*)&Qs[(ty*4+i)*68 + k];
#pragma unroll
            for (int j = 0; j < 4; j++) kv[j] = *(const float4*)&Ks[(tx*4+j)*68 + k];
#pragma unroll
            for (int i = 0; i < 4; i++)
#pragma unroll
                for (int j = 0; j < 4; j++)
                    s[i][j] += qv[i].x*kv[j].x + qv[i].y*kv[j].y
                             + qv[i].z*kv[j].z + qv[i].w*kv[j].w;
        }
        if (kt == 36) {   // only 4 valid keys in the tail tile
#pragma unroll
            for (int j = 0; j < 4; j++)
                if (tx*4 + j >= 4)
#pragma unroll
                    for (int i = 0; i < 4; i++) s[i][j] = -1e30f;
        }
        // online softmax (row groups = 16 lanes sharing ty)
#pragma unroll
        for (int i = 0; i < 4; i++) {
            float rm = fmaxf(fmaxf(s[i][0], s[i][1]), fmaxf(s[i][2], s[i][3]));
#pragma unroll
            for (int off = 8; off; off >>= 1) rm = fmaxf(rm, __shfl_xor_sync(~0u, rm, off, 16));
            float mn = fmaxf(m[i], rm);
            float alpha = __expf(m[i] - mn);
            m[i] = mn;
            float rs = 0.f;
#pragma unroll
            for (int j = 0; j < 4; j++) { s[i][j] = __expf(s[i][j] - mn); rs += s[i][j]; }
#pragma unroll
            for (int off = 8; off; off >>= 1) rs += __shfl_xor_sync(~0u, rs, off, 16);
            l[i] = l[i]*alpha + rs;
#pragma unroll
            for (int j = 0; j < 4; j++) o[i][j] *= alpha;
            float4 pw; pw.x = s[i][0]; pw.y = s[i][1]; pw.z = s[i][2]; pw.w = s[i][3];
            *(float4*)&Ps[(ty*4+i)*68 + tx*4] = pw;
        }
        __syncthreads();
        // O += P @ V
#pragma unroll
        for (int k = 0; k < 64; k += 4) {
            float4 pv[4];
#pragma unroll
            for (int i = 0; i < 4; i++) pv[i] = *(const float4*)&Ps[(ty*4+i)*68 + k];
            float4 v0 = *(const float4*)&Vs[(k+0)*68 + tx*4];
            float4 v1 = *(const float4*)&Vs[(k+1)*68 + tx*4];
            float4 v2 = *(const float4*)&Vs[(k+2)*68 + tx*4];
            float4 v3 = *(const float4*)&Vs[(k+3)*68 + tx*4];
#pragma unroll
            for (int i = 0; i < 4; i++) {
                o[i][0] += pv[i].x*v0.x + pv[i].y*v1.x + pv[i].z*v2.x + pv[i].w*v3.x;
                o[i][1] += pv[i].x*v0.y + pv[i].y*v1.y + pv[i].z*v2.y + pv[i].w*v3.y;
                o[i][2] += pv[i].x*v0.z + pv[i].y*v1.z + pv[i].z*v2.z + pv[i].w*v3.z;
                o[i][3] += pv[i].x*v0.w + pv[i].y*v1.w + pv[i].z*v2.w + pv[i].w*v3.w;
            }
        }
        __syncthreads();
    }
    float* optr = d_ob + ((size_t)b*Nn + qt*64)*HID + h*DH;
#pragma unroll
    for (int i = 0; i < 4; i++) {
        float inv = 1.f / l[i];
        float4 r;
        r.x = o[i][0]*inv; r.y = o[i][1]*inv; r.z = o[i][2]*inv; r.w = o[i][3]*inv;
        *(float4*)(optr + (size_t)(ty*4+i)*HID + tx*4) = r;
    }
}

// ------------------------- output projection GEMM -------------------------
// y[b][c][n] = sum_j w_out[c][j] * o[b][n][j] + b_out[c]   (written transposed for GN2)
__global__ __launch_bounds__(256) void out_gemm_kernel(const float* __restrict__ wout,
                                                       const float* __restrict__ bout) {
    int b  = blockIdx.z;
    int n0 = blockIdx.x * 128;
    int c0 = blockIdx.y * 128;
    const float* Bo = d_ob + (size_t)b*Nn*HID;
    __shared__ __align__(16) float As[16][132];  // [k][c]
    __shared__ __align__(16) float Bs[16][132];  // [k][n]
    int tid = threadIdx.x, ty = tid >> 4, tx = tid & 15;
    float acc[8][8];
#pragma unroll
    for (int i = 0; i < 8; i++)
#pragma unroll
        for (int j = 0; j < 8; j++) acc[i][j] = 0.f;

    for (int k0 = 0; k0 < HID; k0 += 16) {
#pragma unroll
        for (int i = 0; i < 2; i++) {
            int idx = tid + i*256;
            int r = idx >> 2, kk = (idx & 3) << 2;
            float4 v = *(const float4*)(wout + (size_t)(c0+r)*HID + k0 + kk);
            As[kk+0][r] = v.x; As[kk+1][r] = v.y; As[kk+2][r] = v.z; As[kk+3][r] = v.w;
            float4 u = *(const float4*)(Bo + (size_t)(n0+r)*HID + k0 + kk);
            Bs[kk+0][r] = u.x; Bs[kk+1][r] = u.y; Bs[kk+2][r] = u.z; Bs[kk+3][r] = u.w;
        }
        __syncthreads();
#pragma unroll
        for (int kk = 0; kk < 16; kk++) {
            float a[8], bb[8];
            *(float4*)a     = *(const float4*)&As[kk][ty*8];
            *(float4*)(a+4) = *(const float4*)&As[kk][ty*8+4];
            *(float4*)bb     = *(const float4*)&Bs[kk][tx*8];
            *(float4*)(bb+4) = *(const float4*)&Bs[kk][tx*8+4];
#pragma unroll
            for (int i = 0; i < 8; i++)
#pragma unroll
                for (int j = 0; j < 8; j++) acc[i][j] += a[i]*bb[j];
        }
        __syncthreads();
    }
#pragma unroll
    for (int i = 0; i < 8; i++) {
        int c = c0 + ty*8 + i;
        float bo = bout[c];
        float* dst = d_y + ((size_t)b*Cc + c)*Nn + n0 + tx*8;
        float4 v0, v1;
        v0.x = acc[i][0]+bo; v0.y = acc[i][1]+bo; v0.z = acc[i][2]+bo; v0.w = acc[i][3]+bo;
        v1.x = acc[i][4]+bo; v1.y = acc[i][5]+bo; v1.z = acc[i][6]+bo; v1.w = acc[i][7]+bo;
        *(float4*)dst = v0;
        *(float4*)(dst+4) = v1;
    }
}

// ------------------------- GN2 apply -> final output -------------------------
__global__ void gn_apply_kernel(float* __restrict__ out) {
    int f = blockIdx.x * 256 + threadIdx.x;   // float4 index over B*C*N
    float4 v = ((const float4*)d_y)[f];
    int bc = f / (Nn/4);
    float s = d_s2[bc], bb = d_b2[bc];
    float4 r;
    r.x = v.x*s + bb; r.y = v.y*s + bb; r.z = v.z*s + bb; r.w = v.w*s + bb;
    ((float4*)out)[f] = r;
}

// ------------------------- launch -------------------------
extern "C" void kernel_launch(void* const* d_in, const int* in_sizes, int n_in,
                              void* d_out, int out_size) {
    const float* x     = (const float*)d_in[0];
    const float* gn1_w = (const float*)d_in[1];
    const float* gn1_b = (const float*)d_in[2];
    const float* w_qkv = (const float*)d_in[3];
    const float* memkv = (const float*)d_in[4];
    const float* w_out = (const float*)d_in[5];
    const float* b_out = (const float*)d_in[6];
    const float* gn2_w = (const float*)d_in[7];
    const float* gn2_b = (const float*)d_in[8];
    float* out = (float*)d_out;

    static bool attr_set = false;
    if (!attr_set) {
        cudaFuncSetAttribute(flash_kernel, cudaFuncAttributeMaxDynamicSharedMemorySize, 4*64*68*4);
        attr_set = true;
    }

    float *p_s1, *p_b1, *p_s2, *p_b2;
    cudaGetSymbolAddress((void**)&p_s1, d_s1);
    cudaGetSymbolAddress((void**)&p_b1, d_b1);
    cudaGetSymbolAddress((void**)&p_s2, d_s2);
    cudaGetSymbolAddress((void**)&p_b2, d_b2);
    float* p_y;
    cudaGetSymbolAddress((void**)&p_y, d_y);

    gn_stats_kernel<<<Bb*Gg, 256>>>(x, gn1_w, gn1_b, p_s1, p_b1);
    build_weff_kernel<<<dim3(QKVJ, Bb), 128>>>(w_qkv);
    fill_memkv_kernel<<<Bb*NH, 256>>>(memkv);
    qkv_gemm_kernel<<<dim3(Nn/128, QKVJ/128, Bb), 256>>>(x);
    flash_kernel<<<dim3(Nn/64, NH, Bb), 256, 4*64*68*4>>>();
    out_gemm_kernel<<<dim3(Nn/128, Cc/128, Bb), 256>>>(w_out, b_out);
    gn_stats_kernel<<<Bb*Gg, 256>>>(p_y, gn2_w, gn2_b, p_s2, p_b2);
    gn_apply_kernel<<<(Bb*Cc*Nn/4)/256, 256>>>(out);
}

// round 2
// speedup vs baseline: 1.5979x; 1.5979x over previous
#include <cuda_runtime.h>

#define Bb   2
#define Cc   512
#define Nn   2304          // 48*48
#define Gg   32
#define CG   16            // Cc/Gg
#define NH   8
#define DH   64
#define HID  512
#define QKVJ 1536
#define NKV  4
#define Ltot 2308          // Nn + NKV
#define Lpad 2432          // 19*128
#define KT   128
#define NKT  19
#define SCALE 0.125f       // DH^-0.5

// swizzle on word-column within a 128-float row: conflict-free for tx*8 strided float4s
#define SWZ(c) ((c) ^ ((((c) >> 5) & 3) << 2))

// ------------------------- scratch (device globals) -------------------------
__device__ float d_s1[Bb*Cc], d_b1[Bb*Cc], d_s2[Bb*Cc], d_b2[Bb*Cc];
__device__ float d_weff[(size_t)Bb*QKVJ*Cc];
__device__ float d_biasq[Bb*QKVJ];
__device__ float d_q[(size_t)Bb*NH*DH*Nn];     // [b,h][d][token]  (pre-scaled)
__device__ float d_k[(size_t)Bb*NH*DH*Lpad];   // [b,h][d][token]
__device__ float d_v[(size_t)Bb*NH*Lpad*DH];   // [b,h][token][d]
__device__ float d_ob[(size_t)Bb*Nn*HID];
__device__ float d_y[(size_t)Bb*Cc*Nn];

// ------------------------- GroupNorm stats -> affine -------------------------
__global__ void gn_stats_kernel(const float* __restrict__ src,
                                const float* __restrict__ w,
                                const float* __restrict__ bgn,
                                float* __restrict__ sout,
                                float* __restrict__ bout) {
    int b = blockIdx.x >> 5;
    int g = blockIdx.x & 31;
    const float* p = src + ((size_t)b*Cc + g*CG) * Nn;
    float sum = 0.f, sq = 0.f;
    for (int i = threadIdx.x; i < CG*Nn; i += 256) {
        float v = p[i]; sum += v; sq += v*v;
    }
    __shared__ float r0[8], r1[8];
    __shared__ float smu, srs;
    int lane = threadIdx.x & 31, wid = threadIdx.x >> 5;
#pragma unroll
    for (int off = 16; off; off >>= 1) {
        sum += __shfl_xor_sync(~0u, sum, off);
        sq  += __shfl_xor_sync(~0u, sq,  off);
    }
    if (!lane) { r0[wid] = sum; r1[wid] = sq; }
    __syncthreads();
    if (threadIdx.x == 0) {
        float s = 0.f, q = 0.f;
#pragma unroll
        for (int i = 0; i < 8; i++) { s += r0[i]; q += r1[i]; }
        float inv = 1.f / (float)(CG*Nn);
        float mu  = s * inv;
        float var = q * inv - mu*mu;
        smu = mu; srs = rsqrtf(var + 1e-5f);
    }
    __syncthreads();
    if (threadIdx.x < CG) {
        int c = g*CG + threadIdx.x;
        float ww = w[c];
        float sc = srs * ww;
        sout[b*Cc + c] = sc;
        bout[b*Cc + c] = bgn[c] - smu * sc;
    }
}

// ------------------------- fold GN1 affine into W_qkv -------------------------
__global__ void build_weff_kernel(const float* __restrict__ wqkv) {
    int j = blockIdx.x, b = blockIdx.y;
    const float* wr = wqkv + (size_t)j*Cc;
    const float* s  = d_s1 + b*Cc;
    const float* bb = d_b1 + b*Cc;
    float* dst = d_weff + ((size_t)b*QKVJ + j)*Cc;
    float part = 0.f;
    for (int c = threadIdx.x; c < Cc; c += 128) {
        float w = wr[c];
        dst[c] = w * s[c];
        part += w * bb[c];
    }
#pragma unroll
    for (int off = 16; off; off >>= 1) part += __shfl_xor_sync(~0u, part, off);
    __shared__ float r[4];
    if (!(threadIdx.x & 31)) r[threadIdx.x >> 5] = part;
    __syncthreads();
    if (!threadIdx.x) d_biasq[b*QKVJ + j] = r[0]+r[1]+r[2]+r[3];
}

// ------------------------- memory kv prepend + zero pad -------------------------
__global__ void fill_memkv_kernel(const float* __restrict__ mem) {
    int h = blockIdx.x & 7, b = blockIdx.x >> 3;
    float* kdst = d_k + (size_t)(b*NH + h)*DH*Lpad;   // [d][tok]
    float* vdst = d_v + (size_t)(b*NH + h)*Lpad*DH;   // [tok][d]
    int t = threadIdx.x;            // 256 threads == NKV*DH
    {
        int l = t >> 6, d = t & 63;
        kdst[d*Lpad + l]  = mem[((size_t)h*DH + d)*NKV + l];
        vdst[l*DH + d]    = mem[((size_t)(NH + h)*DH + d)*NKV + l];
    }
    const int PADT = Lpad - Ltot;   // 124
    for (int i = t; i < DH*PADT; i += 256) {
        int d = i / PADT, off = i % PADT;
        kdst[d*Lpad + Ltot + off] = 0.f;
    }
    for (int i = t; i < PADT*DH; i += 256) {
        vdst[Ltot*DH + i] = 0.f;
    }
}

// ------------------------- QKV GEMM (128x128x16, 8x8/thread) -------------------------
__global__ __launch_bounds__(256) void qkv_gemm_kernel(const float* __restrict__ x) {
    int b  = blockIdx.z;
    int m0 = blockIdx.x * 128;       // token
    int n0 = blockIdx.y * 128;       // output feature j
    const float* A  = x + (size_t)b*Cc*Nn;            // A[k][m], m contiguous
    const float* Bw = d_weff + (size_t)b*QKVJ*Cc;     // Bw[j][k], k contiguous
    __shared__ __align__(16) float As[16][128];
    __shared__ __align__(16) float Bs[16][132];
    int tid = threadIdx.x;
    int ty = tid >> 4, tx = tid & 15;
    float acc[8][8];
#pragma unroll
    for (int i = 0; i < 8; i++)
#pragma unroll
        for (int j = 0; j < 8; j++) acc[i][j] = 0.f;

    for (int k0 = 0; k0 < Cc; k0 += 16) {
#pragma unroll
        for (int i = 0; i < 2; i++) {
            int idx = tid + i*256;
            int kk = idx >> 5, mm = (idx & 31) << 2;
            *(float4*)&As[kk][mm] = *(const float4*)(A + (size_t)(k0+kk)*Nn + m0 + mm);
        }
#pragma unroll
        for (int i = 0; i < 2; i++) {
            int idx = tid + i*256;
            int j = idx >> 2, kk = (idx & 3) << 2;
            float4 v = *(const float4*)(Bw + (size_t)(n0+j)*Cc + k0 + kk);
            Bs[kk+0][j] = v.x; Bs[kk+1][j] = v.y; Bs[kk+2][j] = v.z; Bs[kk+3][j] = v.w;
        }
        __syncthreads();
#pragma unroll
        for (int kk = 0; kk < 16; kk++) {
            float a[8], bb[8];
            *(float4*)a     = *(const float4*)&As[kk][ty*8];
            *(float4*)(a+4) = *(const float4*)&As[kk][ty*8+4];
            *(float4*)bb     = *(const float4*)&Bs[kk][tx*8];
            *(float4*)(bb+4) = *(const float4*)&Bs[kk][tx*8+4];
#pragma unroll
            for (int i = 0; i < 8; i++)
#pragma unroll
                for (int j = 0; j < 8; j++) acc[i][j] += a[i]*bb[j];
        }
        __syncthreads();
    }
    // epilogue: this thread's 8 output features share (section, head)
    int jg0 = n0 + tx*8;
    int sec = jg0 >> 9;
    int jl  = jg0 & 511;
    int hh  = jl >> 6;
    int dd  = jl & 63;
    float bias[8];
#pragma unroll
    for (int j = 0; j < 8; j++) bias[j] = d_biasq[b*QKVJ + jg0 + j];

    if (sec == 2) {
        // V: [token][d]
        float* base = d_v + (size_t)(b*NH + hh)*Lpad*DH + (size_t)NKV*DH + dd;
#pragma unroll
        for (int i = 0; i < 8; i++) {
            int n = m0 + ty*8 + i;
            float* dst = base + (size_t)n*DH;
            float4 v0, v1;
            v0.x = acc[i][0]+bias[0]; v0.y = acc[i][1]+bias[1];
            v0.z = acc[i][2]+bias[2]; v0.w = acc[i][3]+bias[3];
            v1.x = acc[i][4]+bias[4]; v1.y = acc[i][5]+bias[5];
            v1.z = acc[i][6]+bias[6]; v1.w = acc[i][7]+bias[7];
            *(float4*)dst = v0;
            *(float4*)(dst+4) = v1;
        }
    } else {
        // Q/K transposed: [d][token]; fold softmax scale into Q
        size_t rl = (sec == 0) ? (size_t)Nn : (size_t)Lpad;
        float* base = ((sec == 0) ? d_q : d_k) + (size_t)(b*NH + hh)*DH*rl;
        int tok0 = m0 + ty*8 + ((sec == 0) ? 0 : NKV);
        float mult = (sec == 0) ? SCALE : 1.f;
#pragma unroll
        for (int j = 0; j < 8; j++) {
            float* dst = base + (size_t)(dd+j)*rl + tok0;
            float4 v0, v1;
            v0.x = (acc[0][j]+bias[j])*mult; v0.y = (acc[1][j]+bias[j])*mult;
            v0.z = (acc[2][j]+bias[j])*mult; v0.w = (acc[3][j]+bias[j])*mult;
            v1.x = (acc[4][j]+bias[j])*mult; v1.y = (acc[5][j]+bias[j])*mult;
            v1.z = (acc[6][j]+bias[j])*mult; v1.w = (acc[7][j]+bias[j])*mult;
            *(float4*)dst = v0;
            *(float4*)(dst+4) = v1;
        }
    }
}

// ------------------------- Flash attention (128q x 128k tiles, 8x8) -------------------------
__global__ __launch_bounds__(256, 1) void flash_kernel() {
    extern __shared__ __align__(16) float sm[];
    float* Qs = sm;                 // [64][128]  swizzled cols  (k=d major)
    float* Ks = sm + 8192;          // [64][128]  swizzled cols
    float* Vs = sm + 16384;         // [128][68]
    float* Ps = sm + 25088;         // [128][128] swizzled cols
    int qt = blockIdx.x, h = blockIdx.y, b = blockIdx.z;
    int tid = threadIdx.x, ty = tid >> 4, tx = tid & 15;
    const float* qg = d_q + (size_t)(b*NH + h)*DH*Nn + qt*KT;
    const float* kg = d_k + (size_t)(b*NH + h)*DH*Lpad;
    const float* vg = d_v + (size_t)(b*NH + h)*Lpad*DH;

    const int oA0 = SWZ(ty*8), oA1 = SWZ(ty*8+4);
    const int oB0 = SWZ(tx*8), oB1 = SWZ(tx*8+4);

    // load Q tile [64 d][128 tok]
#pragma unroll
    for (int i = 0; i < 8; i++) {
        int idx = tid + i*256;
        int d = idx >> 5, c4 = (idx & 31) << 2;
        *(float4*)&Qs[d*128 + SWZ(c4)] = *(const float4*)(qg + (size_t)d*Nn + c4);
    }

    float m[8], l[8], o[8][4];
#pragma unroll
    for (int i = 0; i < 8; i++) {
        m[i] = -1e30f; l[i] = 0.f;
        o[i][0] = o[i][1] = o[i][2] = o[i][3] = 0.f;
    }

    for (int kt = 0; kt < NKT; kt++) {
#pragma unroll
        for (int i = 0; i < 8; i++) {
            int idx = tid + i*256;
            int d = idx >> 5, c4 = (idx & 31) << 2;
            *(float4*)&Ks[d*128 + SWZ(c4)] =
                *(const float4*)(kg + (size_t)d*Lpad + kt*KT + c4);
        }
#pragma unroll
        for (int i = 0; i < 8; i++) {
            int idx = tid + i*256;
            int r = idx >> 4, c4 = (idx & 15) << 2;
            *(float4*)&Vs[r*68 + c4] =
                *(const float4*)(vg + (size_t)(kt*KT + r)*DH + c4);
        }
        __syncthreads();

        float s[8][8];
#pragma unroll
        for (int i = 0; i < 8; i++)
#pragma unroll
            for (int j = 0; j < 8; j++) s[i][j] = 0.f;

#pragma unroll 4
        for (int kk = 0; kk < 64; kk++) {
            float a[8], bv[8];
            *(float4*)a      = *(const float4*)&Qs[kk*128 + oA0];
            *(float4*)(a+4)  = *(const float4*)&Qs[kk*128 + oA1];
            *(float4*)bv     = *(const float4*)&Ks[kk*128 + oB0];
            *(float4*)(bv+4) = *(const float4*)&Ks[kk*128 + oB1];
#pragma unroll
            for (int i = 0; i < 8; i++)
#pragma unroll
                for (int j = 0; j < 8; j++) s[i][j] += a[i]*bv[j];
        }

        if (kt == NKT-1) {
#pragma unroll
            for (int jj = 0; jj < 8; jj++)
                if ((NKT-1)*KT + tx*8 + jj >= Ltot)
#pragma unroll
                    for (int i = 0; i < 8; i++) s[i][jj] = -1e30f;
        }

        // online softmax (16 lanes per row group, width-16 shfl)
#pragma unroll
        for (int i = 0; i < 8; i++) {
            float rm = s[i][0];
#pragma unroll
            for (int jj = 1; jj < 8; jj++) rm = fmaxf(rm, s[i][jj]);
#pragma unroll
            for (int off = 8; off; off >>= 1)
                rm = fmaxf(rm, __shfl_xor_sync(~0u, rm, off, 16));
            float mn = fmaxf(m[i], rm);
            float alpha = __expf(m[i] - mn);
            m[i] = mn;
            float rs = 0.f;
#pragma unroll
            for (int jj = 0; jj < 8; jj++) { s[i][jj] = __expf(s[i][jj] - mn); rs += s[i][jj]; }
#pragma unroll
            for (int off = 8; off; off >>= 1)
                rs += __shfl_xor_sync(~0u, rs, off, 16);
            l[i] = l[i]*alpha + rs;
            o[i][0] *= alpha; o[i][1] *= alpha; o[i][2] *= alpha; o[i][3] *= alpha;
            float4 p0, p1;
            p0.x = s[i][0]; p0.y = s[i][1]; p0.z = s[i][2]; p0.w = s[i][3];
            p1.x = s[i][4]; p1.y = s[i][5]; p1.z = s[i][6]; p1.w = s[i][7];
            *(float4*)&Ps[(ty*8+i)*128 + oB0] = p0;
            *(float4*)&Ps[(ty*8+i)*128 + oB1] = p1;
        }
        __syncthreads();

        // O += P @ V   (8 rows x 4 d-cols per thread)
#pragma unroll 4
        for (int j0 = 0; j0 < 128; j0 += 4) {
            float4 v0 = *(const float4*)&Vs[(j0+0)*68 + tx*4];
            float4 v1 = *(const float4*)&Vs[(j0+1)*68 + tx*4];
            float4 v2 = *(const float4*)&Vs[(j0+2)*68 + tx*4];
            float4 v3 = *(const float4*)&Vs[(j0+3)*68 + tx*4];
            int po = SWZ(j0);
#pragma unroll
            for (int ii = 0; ii < 8; ii++) {
                float4 p = *(const float4*)&Ps[(ty*8+ii)*128 + po];
                o[ii][0] += p.x*v0.x + p.y*v1.x + p.z*v2.x + p.w*v3.x;
                o[ii][1] += p.x*v0.y + p.y*v1.y + p.z*v2.y + p.w*v3.y;
                o[ii][2] += p.x*v0.z + p.y*v1.z + p.z*v2.z + p.w*v3.z;
                o[ii][3] += p.x*v0.w + p.y*v1.w + p.z*v2.w + p.w*v3.w;
            }
        }
        __syncthreads();
    }

    float* ob = d_ob + ((size_t)b*Nn + qt*KT)*HID + h*DH;
#pragma unroll
    for (int i = 0; i < 8; i++) {
        float inv = 1.f / l[i];
        float4 r;
        r.x = o[i][0]*inv; r.y = o[i][1]*inv; r.z = o[i][2]*inv; r.w = o[i][3]*inv;
        *(float4*)(ob + (size_t)(ty*8+i)*HID + tx*4) = r;
    }
}

// ------------------------- output projection GEMM -------------------------
__global__ __launch_bounds__(256) void out_gemm_kernel(const float* __restrict__ wout,
                                                       const float* __restrict__ bout) {
    int b  = blockIdx.z;
    int n0 = blockIdx.x * 128;
    int c0 = blockIdx.y * 128;
    const float* Bo = d_ob + (size_t)b*Nn*HID;
    __shared__ __align__(16) float As[16][132];  // [k][c]
    __shared__ __align__(16) float Bs[16][132];  // [k][n]
    int tid = threadIdx.x, ty = tid >> 4, tx = tid & 15;
    float acc[8][8];
#pragma unroll
    for (int i = 0; i < 8; i++)
#pragma unroll
        for (int j = 0; j < 8; j++) acc[i][j] = 0.f;

    for (int k0 = 0; k0 < HID; k0 += 16) {
#pragma unroll
        for (int i = 0; i < 2; i++) {
            int idx = tid + i*256;
            int r = idx >> 2, kk = (idx & 3) << 2;
            float4 v = *(const float4*)(wout + (size_t)(c0+r)*HID + k0 + kk);
            As[kk+0][r] = v.x; As[kk+1][r] = v.y; As[kk+2][r] = v.z; As[kk+3][r] = v.w;
            float4 u = *(const float4*)(Bo + (size_t)(n0+r)*HID + k0 + kk);
            Bs[kk+0][r] = u.x; Bs[kk+1][r] = u.y; Bs[kk+2][r] = u.z; Bs[kk+3][r] = u.w;
        }
        __syncthreads();
#pragma unroll
        for (int kk = 0; kk < 16; kk++) {
            float a[8], bb[8];
            *(float4*)a     = *(const float4*)&As[kk][ty*8];
            *(float4*)(a+4) = *(const float4*)&As[kk][ty*8+4];
            *(float4*)bb     = *(const float4*)&Bs[kk][tx*8];
            *(float4*)(bb+4) = *(const float4*)&Bs[kk][tx*8+4];
#pragma unroll
            for (int i = 0; i < 8; i++)
#pragma unroll
                for (int j = 0; j < 8; j++) acc[i][j] += a[i]*bb[j];
        }
        __syncthreads();
    }
#pragma unroll
    for (int i = 0; i < 8; i++) {
        int c = c0 + ty*8 + i;
        float bo = bout[c];
        float* dst = d_y + ((size_t)b*Cc + c)*Nn + n0 + tx*8;
        float4 v0, v1;
        v0.x = acc[i][0]+bo; v0.y = acc[i][1]+bo; v0.z = acc[i][2]+bo; v0.w = acc[i][3]+bo;
        v1.x = acc[i][4]+bo; v1.y = acc[i][5]+bo; v1.z = acc[i][6]+bo; v1.w = acc[i][7]+bo;
        *(float4*)dst = v0;
        *(float4*)(dst+4) = v1;
    }
}

// ------------------------- GN2 apply -> final output -------------------------
__global__ void gn_apply_kernel(float* __restrict__ out) {
    int f = blockIdx.x * 256 + threadIdx.x;   // float4 index over B*C*N
    float4 v = ((const float4*)d_y)[f];
    int bc = f / (Nn/4);
    float s = d_s2[bc], bb = d_b2[bc];
    float4 r;
    r.x = v.x*s + bb; r.y = v.y*s + bb; r.z = v.z*s + bb; r.w = v.w*s + bb;
    ((float4*)out)[f] = r;
}

// ------------------------- launch -------------------------
extern "C" void kernel_launch(void* const* d_in, const int* in_sizes, int n_in,
                              void* d_out, int out_size) {
    const float* x     = (const float*)d_in[0];
    const float* gn1_w = (const float*)d_in[1];
    const float* gn1_b = (const float*)d_in[2];
    const float* w_qkv = (const float*)d_in[3];
    const float* memkv = (const float*)d_in[4];
    const float* w_out = (const float*)d_in[5];
    const float* b_out = (const float*)d_in[6];
    const float* gn2_w = (const float*)d_in[7];
    const float* gn2_b = (const float*)d_in[8];
    float* out = (float*)d_out;

    const int FLASH_SMEM = (8192 + 8192 + 128*68 + 128*128) * 4;  // 165888 B

    static bool attr_set = false;
    if (!attr_set) {
        cudaFuncSetAttribute(flash_kernel, cudaFuncAttributeMaxDynamicSharedMemorySize, FLASH_SMEM);
        attr_set = true;
    }

    float *p_s1, *p_b1, *p_s2, *p_b2, *p_y;
    cudaGetSymbolAddress((void**)&p_s1, d_s1);
    cudaGetSymbolAddress((void**)&p_b1, d_b1);
    cudaGetSymbolAddress((void**)&p_s2, d_s2);
    cudaGetSymbolAddress((void**)&p_b2, d_b2);
    cudaGetSymbolAddress((void**)&p_y, d_y);

    gn_stats_kernel<<<Bb*Gg, 256>>>(x, gn1_w, gn1_b, p_s1, p_b1);
    build_weff_kernel<<<dim3(QKVJ, Bb), 128>>>(w_qkv);
    fill_memkv_kernel<<<Bb*NH, 256>>>(memkv);
    qkv_gemm_kernel<<<dim3(Nn/128, QKVJ/128, Bb), 256>>>(x);
    flash_kernel<<<dim3(Nn/KT, NH, Bb), 256, FLASH_SMEM>>>();
    out_gemm_kernel<<<dim3(Nn/128, Cc/128, Bb), 256>>>(w_out, b_out);
    gn_stats_kernel<<<Bb*Gg, 256>>>(p_y, gn2_w, gn2_b, p_s2, p_b2);
    gn_apply_kernel<<<(Bb*Cc*Nn/4)/256, 256>>>(out);
}

// round 3
// speedup vs baseline: 1.7056x; 1.0674x over previous
#include <cuda_runtime.h>

#define Bb   2
#define Cc   512
#define Nn   2304          // 48*48
#define Gg   32
#define CG   16            // Cc/Gg
#define NH   8
#define DH   64
#define HID  512
#define QKVJ 1536
#define NKV  4
#define Ltot 2308          // Nn + NKV
#define Lpad 2432          // 19*128
#define KT   128
#define NKT  19
#define SCALE 0.125f       // DH^-0.5

typedef unsigned long long u64;

// swizzle on word-column within a 128-float row: conflict-free for tx*8 strided float4s
#define SWZ(c) ((c) ^ ((((c) >> 5) & 3) << 2))

// ---------- packed f32x2 helpers (FFMA2 path, PTX-only) ----------
__device__ __forceinline__ u64 dupf(float x) {
    u64 r; unsigned xi = __float_as_uint(x);
    asm("mov.b64 %0, {%1, %1};" : "=l"(r) : "r"(xi));
    return r;
}
__device__ __forceinline__ void fma2(u64& d, u64 a, u64 b) {
    asm("fma.rn.f32x2 %0, %1, %2, %0;" : "+l"(d) : "l"(a), "l"(b));
}
__device__ __forceinline__ void mul2(u64& d, u64 a) {
    asm("mul.rn.f32x2 %0, %0, %1;" : "+l"(d) : "l"(a));
}
__device__ __forceinline__ float2 unpk(u64 v) {
    unsigned lo, hi;
    asm("mov.b64 {%0, %1}, %2;" : "=r"(lo), "=r"(hi) : "l"(v));
    return make_float2(__uint_as_float(lo), __uint_as_float(hi));
}

// ------------------------- scratch (device globals) -------------------------
__device__ float d_s1[Bb*Cc], d_b1[Bb*Cc], d_s2[Bb*Cc], d_b2[Bb*Cc];
__device__ float d_weff[(size_t)Bb*QKVJ*Cc];
__device__ float d_biasq[Bb*QKVJ];
__device__ float d_q[(size_t)Bb*NH*DH*Nn];     // [b,h][d][token]  (pre-scaled)
__device__ float d_k[(size_t)Bb*NH*DH*Lpad];   // [b,h][d][token]
__device__ float d_v[(size_t)Bb*NH*Lpad*DH];   // [b,h][token][d]
__device__ float d_ob[(size_t)Bb*Nn*HID];
__device__ float d_y[(size_t)Bb*Cc*Nn];

// ------------------------- GroupNorm stats -> affine -------------------------
__global__ void gn_stats_kernel(const float* __restrict__ src,
                                const float* __restrict__ w,
                                const float* __restrict__ bgn,
                                float* __restrict__ sout,
                                float* __restrict__ bout) {
    int b = blockIdx.x >> 5;
    int g = blockIdx.x & 31;
    const float* p = src + ((size_t)b*Cc + g*CG) * Nn;
    float sum = 0.f, sq = 0.f;
    for (int i = threadIdx.x; i < CG*Nn; i += 256) {
        float v = p[i]; sum += v; sq += v*v;
    }
    __shared__ float r0[8], r1[8];
    __shared__ float smu, srs;
    int lane = threadIdx.x & 31, wid = threadIdx.x >> 5;
#pragma unroll
    for (int off = 16; off; off >>= 1) {
        sum += __shfl_xor_sync(~0u, sum, off);
        sq  += __shfl_xor_sync(~0u, sq,  off);
    }
    if (!lane) { r0[wid] = sum; r1[wid] = sq; }
    __syncthreads();
    if (threadIdx.x == 0) {
        float s = 0.f, q = 0.f;
#pragma unroll
        for (int i = 0; i < 8; i++) { s += r0[i]; q += r1[i]; }
        float inv = 1.f / (float)(CG*Nn);
        float mu  = s * inv;
        float var = q * inv - mu*mu;
        smu = mu; srs = rsqrtf(var + 1e-5f);
    }
    __syncthreads();
    if (threadIdx.x < CG) {
        int c = g*CG + threadIdx.x;
        float ww = w[c];
        float sc = srs * ww;
        sout[b*Cc + c] = sc;
        bout[b*Cc + c] = bgn[c] - smu * sc;
    }
}

// ------------------------- fold GN1 affine into W_qkv -------------------------
__global__ void build_weff_kernel(const float* __restrict__ wqkv) {
    int j = blockIdx.x, b = blockIdx.y;
    const float* wr = wqkv + (size_t)j*Cc;
    const float* s  = d_s1 + b*Cc;
    const float* bb = d_b1 + b*Cc;
    float* dst = d_weff + ((size_t)b*QKVJ + j)*Cc;
    float part = 0.f;
    for (int c = threadIdx.x; c < Cc; c += 128) {
        float w = wr[c];
        dst[c] = w * s[c];
        part += w * bb[c];
    }
#pragma unroll
    for (int off = 16; off; off >>= 1) part += __shfl_xor_sync(~0u, part, off);
    __shared__ float r[4];
    if (!(threadIdx.x & 31)) r[threadIdx.x >> 5] = part;
    __syncthreads();
    if (!threadIdx.x) d_biasq[b*QKVJ + j] = r[0]+r[1]+r[2]+r[3];
}

// ------------------------- memory kv prepend + zero pad -------------------------
__global__ void fill_memkv_kernel(const float* __restrict__ mem) {
    int h = blockIdx.x & 7, b = blockIdx.x >> 3;
    float* kdst = d_k + (size_t)(b*NH + h)*DH*Lpad;   // [d][tok]
    float* vdst = d_v + (size_t)(b*NH + h)*Lpad*DH;   // [tok][d]
    int t = threadIdx.x;            // 256 threads == NKV*DH
    {
        int l = t >> 6, d = t & 63;
        kdst[d*Lpad + l]  = mem[((size_t)h*DH + d)*NKV + l];
        vdst[l*DH + d]    = mem[((size_t)(NH + h)*DH + d)*NKV + l];
    }
    const int PADT = Lpad - Ltot;   // 124
    for (int i = t; i < DH*PADT; i += 256) {
        int d = i / PADT, off = i % PADT;
        kdst[d*Lpad + Ltot + off] = 0.f;
    }
    for (int i = t; i < PADT*DH; i += 256) {
        vdst[Ltot*DH + i] = 0.f;
    }
}

// ------------------------- QKV GEMM (128x128x16, 8x8/thread, FFMA2) -------------------------
__global__ __launch_bounds__(256) void qkv_gemm_kernel(const float* __restrict__ x) {
    int b  = blockIdx.z;
    int m0 = blockIdx.x * 128;       // token
    int n0 = blockIdx.y * 128;       // output feature j
    const float* A  = x + (size_t)b*Cc*Nn;            // A[k][m], m contiguous
    const float* Bw = d_weff + (size_t)b*QKVJ*Cc;     // Bw[j][k], k contiguous
    __shared__ __align__(16) float As[16][128];
    __shared__ __align__(16) float Bs[16][132];       // 132*4 = 528 = 33*16 (16B aligned rows)
    int tid = threadIdx.x;
    int ty = tid >> 4, tx = tid & 15;
    u64 acc2[8][4];
#pragma unroll
    for (int i = 0; i < 8; i++)
#pragma unroll
        for (int j = 0; j < 4; j++) acc2[i][j] = 0ULL;

    for (int k0 = 0; k0 < Cc; k0 += 16) {
#pragma unroll
        for (int i = 0; i < 2; i++) {
            int idx = tid + i*256;
            int kk = idx >> 5, mm = (idx & 31) << 2;
            *(float4*)&As[kk][mm] = *(const float4*)(A + (size_t)(k0+kk)*Nn + m0 + mm);
        }
#pragma unroll
        for (int i = 0; i < 2; i++) {
            int idx = tid + i*256;
            int j = idx >> 2, kk = (idx & 3) << 2;
            float4 v = *(const float4*)(Bw + (size_t)(n0+j)*Cc + k0 + kk);
            Bs[kk+0][j] = v.x; Bs[kk+1][j] = v.y; Bs[kk+2][j] = v.z; Bs[kk+3][j] = v.w;
        }
        __syncthreads();
#pragma unroll
        for (int kk = 0; kk < 16; kk++) {
            float a[8];
            *(float4*)a     = *(const float4*)&As[kk][ty*8];
            *(float4*)(a+4) = *(const float4*)&As[kk][ty*8+4];
            ulonglong2 b0 = *(const ulonglong2*)&Bs[kk][tx*8];
            ulonglong2 b1 = *(const ulonglong2*)&Bs[kk][tx*8+4];
#pragma unroll
            for (int i = 0; i < 8; i++) {
                u64 ad = dupf(a[i]);
                fma2(acc2[i][0], ad, b0.x);
                fma2(acc2[i][1], ad, b0.y);
                fma2(acc2[i][2], ad, b1.x);
                fma2(acc2[i][3], ad, b1.y);
            }
        }
        __syncthreads();
    }
    // epilogue: this thread's 8 output features share (section, head)
    int jg0 = n0 + tx*8;
    int sec = jg0 >> 9;
    int jl  = jg0 & 511;
    int hh  = jl >> 6;
    int dd  = jl & 63;
    float bias[8];
#pragma unroll
    for (int j = 0; j < 8; j++) bias[j] = d_biasq[b*QKVJ + jg0 + j];

    if (sec == 2) {
        // V: [token][d] — row-wise writes
        float* base = d_v + (size_t)(b*NH + hh)*Lpad*DH + (size_t)NKV*DH + dd;
#pragma unroll
        for (int i = 0; i < 8; i++) {
            int n = m0 + ty*8 + i;
            float* dst = base + (size_t)n*DH;
            float2 c0 = unpk(acc2[i][0]), c1 = unpk(acc2[i][1]);
            float2 c2 = unpk(acc2[i][2]), c3 = unpk(acc2[i][3]);
            float4 v0, v1;
            v0.x = c0.x+bias[0]; v0.y = c0.y+bias[1];
            v0.z = c1.x+bias[2]; v0.w = c1.y+bias[3];
            v1.x = c2.x+bias[4]; v1.y = c2.y+bias[5];
            v1.z = c3.x+bias[6]; v1.w = c3.y+bias[7];
            *(float4*)dst = v0;
            *(float4*)(dst+4) = v1;
        }
    } else {
        // Q/K transposed: [d][token]; fold softmax scale into Q
        size_t rl = (sec == 0) ? (size_t)Nn : (size_t)Lpad;
        float* base = ((sec == 0) ? d_q : d_k) + (size_t)(b*NH + hh)*DH*rl;
        int tok0 = m0 + ty*8 + ((sec == 0) ? 0 : NKV);
        float mult = (sec == 0) ? SCALE : 1.f;
#pragma unroll
        for (int j2 = 0; j2 < 4; j2++) {
            float c0[8], c1[8];
#pragma unroll
            for (int i = 0; i < 8; i++) {
                float2 c = unpk(acc2[i][j2]);
                c0[i] = c.x; c1[i] = c.y;
            }
            int j = j2*2;
            float* dst0 = base + (size_t)(dd+j)*rl + tok0;
            float* dst1 = base + (size_t)(dd+j+1)*rl + tok0;
            float4 w0, w1;
            w0.x = (c0[0]+bias[j])*mult; w0.y = (c0[1]+bias[j])*mult;
            w0.z = (c0[2]+bias[j])*mult; w0.w = (c0[3]+bias[j])*mult;
            w1.x = (c0[4]+bias[j])*mult; w1.y = (c0[5]+bias[j])*mult;
            w1.z = (c0[6]+bias[j])*mult; w1.w = (c0[7]+bias[j])*mult;
            *(float4*)dst0 = w0; *(float4*)(dst0+4) = w1;
            w0.x = (c1[0]+bias[j+1])*mult; w0.y = (c1[1]+bias[j+1])*mult;
            w0.z = (c1[2]+bias[j+1])*mult; w0.w = (c1[3]+bias[j+1])*mult;
            w1.x = (c1[4]+bias[j+1])*mult; w1.y = (c1[5]+bias[j+1])*mult;
            w1.z = (c1[6]+bias[j+1])*mult; w1.w = (c1[7]+bias[j+1])*mult;
            *(float4*)dst1 = w0; *(float4*)(dst1+4) = w1;
        }
    }
}

// ------------------------- Flash attention (128q x 128k tiles, 8x8, FFMA2) -------------------------
__global__ __launch_bounds__(256, 1) void flash_kernel() {
    extern __shared__ __align__(16) float sm[];
    float* Qs = sm;                 // [64][128]  swizzled cols  (k=d major)
    float* Ks = sm + 8192;          // [64][128]  swizzled cols
    float* Vs = sm + 16384;         // [128][68]
    float* Ps = sm + 25088;         // [128][128] swizzled cols
    int qt = blockIdx.x, h = blockIdx.y, b = blockIdx.z;
    int tid = threadIdx.x, ty = tid >> 4, tx = tid & 15;
    const float* qg = d_q + (size_t)(b*NH + h)*DH*Nn + qt*KT;
    const float* kg = d_k + (size_t)(b*NH + h)*DH*Lpad;
    const float* vg = d_v + (size_t)(b*NH + h)*Lpad*DH;

    const int oA0 = SWZ(ty*8), oA1 = SWZ(ty*8+4);
    const int oB0 = SWZ(tx*8), oB1 = SWZ(tx*8+4);

    // load Q tile [64 d][128 tok]
#pragma unroll
    for (int i = 0; i < 8; i++) {
        int idx = tid + i*256;
        int d = idx >> 5, c4 = (idx & 31) << 2;
        *(float4*)&Qs[d*128 + SWZ(c4)] = *(const float4*)(qg + (size_t)d*Nn + c4);
    }

    float m[8], l[8];
    u64 o2[8][2];
#pragma unroll
    for (int i = 0; i < 8; i++) {
        m[i] = -1e30f; l[i] = 0.f;
        o2[i][0] = 0ULL; o2[i][1] = 0ULL;
    }

    for (int kt = 0; kt < NKT; kt++) {
#pragma unroll
        for (int i = 0; i < 8; i++) {
            int idx = tid + i*256;
            int d = idx >> 5, c4 = (idx & 31) << 2;
            *(float4*)&Ks[d*128 + SWZ(c4)] =
                *(const float4*)(kg + (size_t)d*Lpad + kt*KT + c4);
        }
#pragma unroll
        for (int i = 0; i < 8; i++) {
            int idx = tid + i*256;
            int r = idx >> 4, c4 = (idx & 15) << 2;
            *(float4*)&Vs[r*68 + c4] =
                *(const float4*)(vg + (size_t)(kt*KT + r)*DH + c4);
        }
        __syncthreads();

        u64 s2[8][4];
#pragma unroll
        for (int i = 0; i < 8; i++)
#pragma unroll
            for (int j = 0; j < 4; j++) s2[i][j] = 0ULL;

#pragma unroll 4
        for (int kk = 0; kk < 64; kk++) {
            float a[8];
            *(float4*)a      = *(const float4*)&Qs[kk*128 + oA0];
            *(float4*)(a+4)  = *(const float4*)&Qs[kk*128 + oA1];
            ulonglong2 b0 = *(const ulonglong2*)&Ks[kk*128 + oB0];
            ulonglong2 b1 = *(const ulonglong2*)&Ks[kk*128 + oB1];
#pragma unroll
            for (int i = 0; i < 8; i++) {
                u64 ad = dupf(a[i]);
                fma2(s2[i][0], ad, b0.x);
                fma2(s2[i][1], ad, b0.y);
                fma2(s2[i][2], ad, b1.x);
                fma2(s2[i][3], ad, b1.y);
            }
        }

        float s[8][8];
#pragma unroll
        for (int i = 0; i < 8; i++) {
#pragma unroll
            for (int j2 = 0; j2 < 4; j2++) {
                float2 c = unpk(s2[i][j2]);
                s[i][j2*2] = c.x; s[i][j2*2+1] = c.y;
            }
        }

        if (kt == NKT-1) {
#pragma unroll
            for (int jj = 0; jj < 8; jj++)
                if ((NKT-1)*KT + tx*8 + jj >= Ltot)
#pragma unroll
                    for (int i = 0; i < 8; i++) s[i][jj] = -1e30f;
        }

        // online softmax (16 lanes per row group, width-16 shfl)
#pragma unroll
        for (int i = 0; i < 8; i++) {
            float rm = s[i][0];
#pragma unroll
            for (int jj = 1; jj < 8; jj++) rm = fmaxf(rm, s[i][jj]);
#pragma unroll
            for (int off = 8; off; off >>= 1)
                rm = fmaxf(rm, __shfl_xor_sync(~0u, rm, off, 16));
            float mn = fmaxf(m[i], rm);
            float alpha = __expf(m[i] - mn);
            m[i] = mn;
            float rs = 0.f;
#pragma unroll
            for (int jj = 0; jj < 8; jj++) { s[i][jj] = __expf(s[i][jj] - mn); rs += s[i][jj]; }
#pragma unroll
            for (int off = 8; off; off >>= 1)
                rs += __shfl_xor_sync(~0u, rs, off, 16);
            l[i] = l[i]*alpha + rs;
            u64 ad = dupf(alpha);
            mul2(o2[i][0], ad); mul2(o2[i][1], ad);
            float4 p0, p1;
            p0.x = s[i][0]; p0.y = s[i][1]; p0.z = s[i][2]; p0.w = s[i][3];
            p1.x = s[i][4]; p1.y = s[i][5]; p1.z = s[i][6]; p1.w = s[i][7];
            *(float4*)&Ps[(ty*8+i)*128 + oB0] = p0;
            *(float4*)&Ps[(ty*8+i)*128 + oB1] = p1;
        }
        __syncthreads();

        // O += P @ V   (8 rows x 4 d-cols per thread, d paired)
#pragma unroll 4
        for (int j0 = 0; j0 < 128; j0 += 4) {
            ulonglong2 v0 = *(const ulonglong2*)&Vs[(j0+0)*68 + tx*4];
            ulonglong2 v1 = *(const ulonglong2*)&Vs[(j0+1)*68 + tx*4];
            ulonglong2 v2 = *(const ulonglong2*)&Vs[(j0+2)*68 + tx*4];
            ulonglong2 v3 = *(const ulonglong2*)&Vs[(j0+3)*68 + tx*4];
            int po = SWZ(j0);
#pragma unroll
            for (int ii = 0; ii < 8; ii++) {
                float4 p = *(const float4*)&Ps[(ty*8+ii)*128 + po];
                u64 px = dupf(p.x), py = dupf(p.y), pz = dupf(p.z), pw = dupf(p.w);
                fma2(o2[ii][0], px, v0.x); fma2(o2[ii][1], px, v0.y);
                fma2(o2[ii][0], py, v1.x); fma2(o2[ii][1], py, v1.y);
                fma2(o2[ii][0], pz, v2.x); fma2(o2[ii][1], pz, v2.y);
                fma2(o2[ii][0], pw, v3.x); fma2(o2[ii][1], pw, v3.y);
            }
        }
        __syncthreads();
    }

    float* ob = d_ob + ((size_t)b*Nn + qt*KT)*HID + h*DH;
#pragma unroll
    for (int i = 0; i < 8; i++) {
        float inv = 1.f / l[i];
        float2 c0 = unpk(o2[i][0]), c1 = unpk(o2[i][1]);
        float4 r;
        r.x = c0.x*inv; r.y = c0.y*inv; r.z = c1.x*inv; r.w = c1.y*inv;
        *(float4*)(ob + (size_t)(ty*8+i)*HID + tx*4) = r;
    }
}

// ------------------------- output projection GEMM (FFMA2) -------------------------
__global__ __launch_bounds__(256) void out_gemm_kernel(const float* __restrict__ wout,
                                                       const float* __restrict__ bout) {
    int b  = blockIdx.z;
    int n0 = blockIdx.x * 128;
    int c0 = blockIdx.y * 128;
    const float* Bo = d_ob + (size_t)b*Nn*HID;
    __shared__ __align__(16) float As[16][132];  // [k][c]
    __shared__ __align__(16) float Bs[16][132];  // [k][n]
    int tid = threadIdx.x, ty = tid >> 4, tx = tid & 15;
    u64 acc2[8][4];
#pragma unroll
    for (int i = 0; i < 8; i++)
#pragma unroll
        for (int j = 0; j < 4; j++) acc2[i][j] = 0ULL;

    for (int k0 = 0; k0 < HID; k0 += 16) {
#pragma unroll
        for (int i = 0; i < 2; i++) {
            int idx = tid + i*256;
            int r = idx >> 2, kk = (idx & 3) << 2;
            float4 v = *(const float4*)(wout + (size_t)(c0+r)*HID + k0 + kk);
            As[kk+0][r] = v.x; As[kk+1][r] = v.y; As[kk+2][r] = v.z; As[kk+3][r] = v.w;
            float4 u = *(const float4*)(Bo + (size_t)(n0+r)*HID + k0 + kk);
            Bs[kk+0][r] = u.x; Bs[kk+1][r] = u.y; Bs[kk+2][r] = u.z; Bs[kk+3][r] = u.w;
        }
        __syncthreads();
#pragma unroll
        for (int kk = 0; kk < 16; kk++) {
            float a[8];
            *(float4*)a     = *(const float4*)&As[kk][ty*8];
            *(float4*)(a+4) = *(const float4*)&As[kk][ty*8+4];
            ulonglong2 b0 = *(const ulonglong2*)&Bs[kk][tx*8];
            ulonglong2 b1 = *(const ulonglong2*)&Bs[kk][tx*8+4];
#pragma unroll
            for (int i = 0; i < 8; i++) {
                u64 ad = dupf(a[i]);
                fma2(acc2[i][0], ad, b0.x);
                fma2(acc2[i][1], ad, b0.y);
                fma2(acc2[i][2], ad, b1.x);
                fma2(acc2[i][3], ad, b1.y);
            }
        }
        __syncthreads();
    }
#pragma unroll
    for (int i = 0; i < 8; i++) {
        int c = c0 + ty*8 + i;
        float bo = bout[c];
        float* dst = d_y + ((size_t)b*Cc + c)*Nn + n0 + tx*8;
        float2 c0f = unpk(acc2[i][0]), c1f = unpk(acc2[i][1]);
        float2 c2f = unpk(acc2[i][2]), c3f = unpk(acc2[i][3]);
        float4 v0, v1;
        v0.x = c0f.x+bo; v0.y = c0f.y+bo; v0.z = c1f.x+bo; v0.w = c1f.y+bo;
        v1.x = c2f.x+bo; v1.y = c2f.y+bo; v1.z = c3f.x+bo; v1.w = c3f.y+bo;
        *(float4*)dst = v0;
        *(float4*)(dst+4) = v1;
    }
}

// ------------------------- GN2 apply -> final output -------------------------
__global__ void gn_apply_kernel(float* __restrict__ out) {
    int f = blockIdx.x * 256 + threadIdx.x;   // float4 index over B*C*N
    float4 v = ((const float4*)d_y)[f];
    int bc = f / (Nn/4);
    float s = d_s2[bc], bb = d_b2[bc];
    float4 r;
    r.x = v.x*s + bb; r.y = v.y*s + bb; r.z = v.z*s + bb; r.w = v.w*s + bb;
    ((float4*)out)[f] = r;
}

// ------------------------- launch -------------------------
extern "C" void kernel_launch(void* const* d_in, const int* in_sizes, int n_in,
                              void* d_out, int out_size) {
    const float* x     = (const float*)d_in[0];
    const float* gn1_w = (const float*)d_in[1];
    const float* gn1_b = (const float*)d_in[2];
    const float* w_qkv = (const float*)d_in[3];
    const float* memkv = (const float*)d_in[4];
    const float* w_out = (const float*)d_in[5];
    const float* b_out = (const float*)d_in[6];
    const float* gn2_w = (const float*)d_in[7];
    const float* gn2_b = (const float*)d_in[8];
    float* out = (float*)d_out;

    const int FLASH_SMEM = (8192 + 8192 + 128*68 + 128*128) * 4;  // 165888 B

    static bool attr_set = false;
    if (!attr_set) {
        cudaFuncSetAttribute(flash_kernel, cudaFuncAttributeMaxDynamicSharedMemorySize, FLASH_SMEM);
        attr_set = true;
    }

    float *p_s1, *p_b1, *p_s2, *p_b2, *p_y;
    cudaGetSymbolAddress((void**)&p_s1, d_s1);
    cudaGetSymbolAddress((void**)&p_b1, d_b1);
    cudaGetSymbolAddress((void**)&p_s2, d_s2);
    cudaGetSymbolAddress((void**)&p_b2, d_b2);
    cudaGetSymbolAddress((void**)&p_y, d_y);

    gn_stats_kernel<<<Bb*Gg, 256>>>(x, gn1_w, gn1_b, p_s1, p_b1);
    build_weff_kernel<<<dim3(QKVJ, Bb), 128>>>(w_qkv);
    fill_memkv_kernel<<<Bb*NH, 256>>>(memkv);
    qkv_gemm_kernel<<<dim3(Nn/128, QKVJ/128, Bb), 256>>>(x);
    flash_kernel<<<dim3(Nn/KT, NH, Bb), 256, FLASH_SMEM>>>();
    out_gemm_kernel<<<dim3(Nn/128, Cc/128, Bb), 256>>>(w_out, b_out);
    gn_stats_kernel<<<Bb*Gg, 256>>>(p_y, gn2_w, gn2_b, p_s2, p_b2);
    gn_apply_kernel<<<(Bb*Cc*Nn/4)/256, 256>>>(out);
}

// round 5
// speedup vs baseline: 2.0826x; 1.2211x over previous
#include <cuda_runtime.h>
#include <cuda_bf16.h>
#include <cstdint>

#define Bb   2
#define Cc   512
#define Nn   2304          // 48*48
#define Gg   32
#define CG   16            // Cc/Gg
#define NH   8
#define DH   64
#define HID  512
#define QKVJ 1536
#define NKV  4
#define Ltot 2308          // Nn + NKV
#define Lpad 2432          // 19*128
#define KT   128
#define NKT  19
#define SCALE 0.125f       // DH^-0.5

typedef unsigned long long u64;
typedef __nv_bfloat16 bf16;

// swizzle on word-column within a 128-float row (flash kernel smem)
#define SWZ(c) ((c) ^ ((((c) >> 5) & 3) << 2))
// byte swizzle for 128-byte rows (mma smem tiles)
#define SW128B(o) ((o) ^ (((o) >> 3) & 0x70))

// ---------- packed f32x2 helpers (flash kernel) ----------
__device__ __forceinline__ u64 dupf(float x) {
    u64 r; unsigned xi = __float_as_uint(x);
    asm("mov.b64 %0, {%1, %1};" : "=l"(r) : "r"(xi));
    return r;
}
__device__ __forceinline__ void fma2(u64& d, u64 a, u64 b) {
    asm("fma.rn.f32x2 %0, %1, %2, %0;" : "+l"(d) : "l"(a), "l"(b));
}
__device__ __forceinline__ void mul2(u64& d, u64 a) {
    asm("mul.rn.f32x2 %0, %0, %1;" : "+l"(d) : "l"(a));
}
__device__ __forceinline__ float2 unpk(u64 v) {
    unsigned lo, hi;
    asm("mov.b64 {%0, %1}, %2;" : "=r"(lo), "=r"(hi) : "l"(v));
    return make_float2(__uint_as_float(lo), __uint_as_float(hi));
}

// ---------- mma.sync helpers (arch-portable tensor path) ----------
__device__ __forceinline__ uint32_t smem_u32_of(const void* p) {
    uint32_t a;
    asm("{ .reg .u64 t; cvta.to.shared.u64 t, %1; cvt.u32.u64 %0, t; }" : "=r"(a) : "l"(p));
    return a;
}
__device__ __forceinline__ void ldm_x4(uint32_t r[4], uint32_t a) {
    asm volatile("ldmatrix.sync.aligned.m8n8.x4.shared.b16 {%0,%1,%2,%3}, [%4];"
        : "=r"(r[0]), "=r"(r[1]), "=r"(r[2]), "=r"(r[3]) : "r"(a));
}
__device__ __forceinline__ void ldm_x2(uint32_t r[2], uint32_t a) {
    asm volatile("ldmatrix.sync.aligned.m8n8.x2.shared.b16 {%0,%1}, [%2];"
        : "=r"(r[0]), "=r"(r[1]) : "r"(a));
}
__device__ __forceinline__ void mma_bf16(float d[4], const uint32_t a[4], const uint32_t b[2]) {
    asm volatile(
        "mma.sync.aligned.m16n8k16.row.col.f32.bf16.bf16.f32 "
        "{%0,%1,%2,%3}, {%4,%5,%6,%7}, {%8,%9}, {%0,%1,%2,%3};"
        : "+f"(d[0]), "+f"(d[1]), "+f"(d[2]), "+f"(d[3])
        : "r"(a[0]), "r"(a[1]), "r"(a[2]), "r"(a[3]), "r"(b[0]), "r"(b[1]));
}

// ------------------------- scratch (device globals) -------------------------
__device__ float d_s1[Bb*Cc], d_b1[Bb*Cc], d_s2[Bb*Cc], d_b2[Bb*Cc];
__device__ bf16 d_thi[(size_t)Bb*Nn*Cc],  d_tlo[(size_t)Bb*Nn*Cc];   // tokens [b][tok][c]
__device__ bf16 d_whi[(size_t)QKVJ*Cc],   d_wlo[(size_t)QKVJ*Cc];    // w_qkv  [j][c]
__device__ bf16 d_wohi[(size_t)Cc*HID],   d_wolo[(size_t)Cc*HID];    // w_out  [c][j]
__device__ float d_q[(size_t)Bb*NH*DH*Nn];     // [b,h][d][token]  (pre-scaled)
__device__ float d_k[(size_t)Bb*NH*DH*Lpad];   // [b,h][d][token]
__device__ float d_v[(size_t)Bb*NH*Lpad*DH];   // [b,h][token][d]
__device__ bf16 d_ohi[(size_t)Bb*Nn*HID], d_olo[(size_t)Bb*Nn*HID];  // attn out [b][tok][j]
__device__ float d_y[(size_t)Bb*Cc*Nn];

// ------------------------- GroupNorm stats -> affine -------------------------
__global__ void gn_stats_kernel(const float* __restrict__ src,
                                const float* __restrict__ w,
                                const float* __restrict__ bgn,
                                float* __restrict__ sout,
                                float* __restrict__ bout) {
    int b = blockIdx.x >> 5;
    int g = blockIdx.x & 31;
    const float* p = src + ((size_t)b*Cc + g*CG) * Nn;
    float sum = 0.f, sq = 0.f;
    for (int i = threadIdx.x; i < CG*Nn; i += 256) {
        float v = p[i]; sum += v; sq += v*v;
    }
    __shared__ float r0[8], r1[8];
    __shared__ float smu, srs;
    int lane = threadIdx.x & 31, wid = threadIdx.x >> 5;
#pragma unroll
    for (int off = 16; off; off >>= 1) {
        sum += __shfl_xor_sync(~0u, sum, off);
        sq  += __shfl_xor_sync(~0u, sq,  off);
    }
    if (!lane) { r0[wid] = sum; r1[wid] = sq; }
    __syncthreads();
    if (threadIdx.x == 0) {
        float s = 0.f, q = 0.f;
#pragma unroll
        for (int i = 0; i < 8; i++) { s += r0[i]; q += r1[i]; }
        float inv = 1.f / (float)(CG*Nn);
        float mu  = s * inv;
        float var = q * inv - mu*mu;
        smu = mu; srs = rsqrtf(var + 1e-5f);
    }
    __syncthreads();
    if (threadIdx.x < CG) {
        int c = g*CG + threadIdx.x;
        float ww = w[c];
        float sc = srs * ww;
        sout[b*Cc + c] = sc;
        bout[b*Cc + c] = bgn[c] - smu * sc;
    }
}

// ------------------------- prep: transpose x + GN1 affine + bf16 split -------------------------
__global__ void prep_x_kernel(const float* __restrict__ x) {
    __shared__ float t[32][33];
    int b = blockIdx.z;
    int c0 = blockIdx.y * 32;
    int t0 = blockIdx.x * 32;
    int lx = threadIdx.x & 31, ly = threadIdx.x >> 5;   // 8 rows
#pragma unroll
    for (int i = 0; i < 4; i++) {
        int c = c0 + ly + i*8;
        float v = x[((size_t)b*Cc + c)*Nn + t0 + lx];
        t[ly + i*8][lx] = v * d_s1[b*Cc + c] + d_b1[b*Cc + c];
    }
    __syncthreads();
#pragma unroll
    for (int i = 0; i < 4; i++) {
        int tok = t0 + ly + i*8;
        int c = c0 + lx;
        float v = t[lx][ly + i*8];
        bf16 hi = __float2bfloat16(v);
        bf16 lo = __float2bfloat16(v - __bfloat162float(hi));
        size_t idx = ((size_t)b*Nn + tok)*Cc + c;
        d_thi[idx] = hi; d_tlo[idx] = lo;
    }
}

// ------------------------- prep: split an fp32 matrix into bf16 hi/lo -------------------------
__global__ void split_kernel(const float* __restrict__ src,
                             bf16* __restrict__ hi,
                             bf16* __restrict__ lo) {
    int i = blockIdx.x * 256 + threadIdx.x;
    float v = src[i];
    bf16 h = __float2bfloat16(v);
    hi[i] = h;
    lo[i] = __float2bfloat16(v - __bfloat162float(h));
}

// ------------------------- memory kv prepend + zero pad -------------------------
__global__ void fill_memkv_kernel(const float* __restrict__ mem) {
    int h = blockIdx.x & 7, b = blockIdx.x >> 3;
    float* kdst = d_k + (size_t)(b*NH + h)*DH*Lpad;   // [d][tok]
    float* vdst = d_v + (size_t)(b*NH + h)*Lpad*DH;   // [tok][d]
    int t = threadIdx.x;            // 256 threads == NKV*DH
    {
        int l = t >> 6, d = t & 63;
        kdst[d*Lpad + l]  = mem[((size_t)h*DH + d)*NKV + l];
        vdst[l*DH + d]    = mem[((size_t)(NH + h)*DH + d)*NKV + l];
    }
    const int PADT = Lpad - Ltot;   // 124
    for (int i = t; i < DH*PADT; i += 256) {
        int d = i / PADT, off = i % PADT;
        kdst[d*Lpad + Ltot + off] = 0.f;
    }
    for (int i = t; i < PADT*DH; i += 256) {
        vdst[Ltot*DH + i] = 0.f;
    }
}

// ------------------------- bf16x3 mma.sync mainloop -------------------------
// D[128,128] = A[128,512] · B[128,512]^T, hi/lo split.
// 8 warps, each 64x32 (4x4 m16n8k16 tiles). smem: 4 tiles of [128][64] bf16 (16KB each).
#define SA_HI 0u
#define SA_LO 16384u
#define SB_HI 32768u
#define SB_LO 49152u

__device__ __forceinline__ void gemm_bf16x3_acc(
    const bf16* __restrict__ Ahi, const bf16* __restrict__ Alo,
    const bf16* __restrict__ Bhi, const bf16* __restrict__ Blo,
    char* smem, float acc[4][4][4])
{
    const int tid = threadIdx.x;
    const int w = tid >> 5, l = tid & 31;
    const int mb = (w >> 2) * 64, nb = (w & 3) * 32;
    const uint32_t sbase = smem_u32_of(smem);

    const int arow = (l & 7) + ((l >> 3) & 1) * 8;
    const int acol = (l & 16) ? 16 : 0;
    const int brow = l & 7;
    const int bcol = (l & 8) ? 16 : 0;

    const bf16* srcs[4] = {Ahi, Alo, Bhi, Blo};

    for (int ch = 0; ch < 8; ch++) {
        if (ch) __syncthreads();
        int k0 = ch * 64;
#pragma unroll
        for (int tI = 0; tI < 4; tI++) {
            const char* src = (const char*)srcs[tI] + k0*2;
            uint32_t tb = tI * 16384u;
#pragma unroll
            for (int it = 0; it < 4; it++) {
                int idx = tid + it*256;
                int row = idx >> 3, u = idx & 7;
                uint4 v = *(const uint4*)(src + (size_t)row*1024 + u*16);
                uint32_t boff = (uint32_t)row*128u + (uint32_t)u*16u;
                *(uint4*)(smem + tb + SW128B(boff)) = v;
            }
        }
        __syncthreads();

#pragma unroll
        for (int ks = 0; ks < 4; ks++) {
            int kb = ks * 32;
            uint32_t ah[4][4], al[4][4];
#pragma unroll
            for (int mt = 0; mt < 4; mt++) {
                uint32_t off = SW128B((uint32_t)(mb + mt*16 + arow)*128u + kb + acol);
                ldm_x4(ah[mt], sbase + SA_HI + off);
                ldm_x4(al[mt], sbase + SA_LO + off);
            }
            uint32_t bh[4][2], bl[4][2];
#pragma unroll
            for (int nt = 0; nt < 4; nt++) {
                uint32_t off = SW128B((uint32_t)(nb + nt*8 + brow)*128u + kb + bcol);
                ldm_x2(bh[nt], sbase + SB_HI + off);
                ldm_x2(bl[nt], sbase + SB_LO + off);
            }
#pragma unroll
            for (int mt = 0; mt < 4; mt++)
#pragma unroll
                for (int nt = 0; nt < 4; nt++) {
                    mma_bf16(acc[mt][nt], ah[mt], bh[nt]);
                    mma_bf16(acc[mt][nt], al[mt], bh[nt]);
                    mma_bf16(acc[mt][nt], ah[mt], bl[nt]);
                }
        }
    }
}

// ------------------------- QKV GEMM (mma.sync bf16x3) -------------------------
__global__ __launch_bounds__(256, 1) void qkv_mma_kernel() {
    extern __shared__ __align__(16) char smem[];
    int b = blockIdx.z, m0 = blockIdx.x * 128, n0 = blockIdx.y * 128;

    float acc[4][4][4];
#pragma unroll
    for (int i = 0; i < 4; i++)
#pragma unroll
        for (int j = 0; j < 4; j++)
#pragma unroll
            for (int r = 0; r < 4; r++) acc[i][j][r] = 0.f;

    gemm_bf16x3_acc(d_thi + ((size_t)b*Nn + m0)*Cc, d_tlo + ((size_t)b*Nn + m0)*Cc,
                    d_whi + (size_t)n0*Cc,          d_wlo + (size_t)n0*Cc,
                    smem, acc);

    const int tid = threadIdx.x, w = tid >> 5, l = tid & 31;
    const int mb = (w >> 2) * 64, nb = (w & 3) * 32;
    const int trow = l >> 2, tcol = (l & 3) * 2;
    const int sec = n0 >> 9;     // 0=q 1=k 2=v
    const float mult = (sec == 0) ? SCALE : 1.f;

#pragma unroll
    for (int mt = 0; mt < 4; mt++) {
#pragma unroll
        for (int nt = 0; nt < 4; nt++) {
            int tok = m0 + mb + mt*16 + trow;
            int j   = n0 + nb + nt*8 + tcol;
            int jl  = j & 511;
            int hh  = jl >> 6, dd = jl & 63;
            float* acc4 = acc[mt][nt];
            if (sec == 2) {
                float* base = d_v + ((size_t)(b*NH + hh)*Lpad + NKV)*DH + dd;
                *(float2*)(base + (size_t)tok*DH)     = make_float2(acc4[0], acc4[1]);
                *(float2*)(base + (size_t)(tok+8)*DH) = make_float2(acc4[2], acc4[3]);
            } else {
                size_t rl = (sec == 0) ? (size_t)Nn : (size_t)Lpad;
                float* base = (sec == 0)
                    ? d_q + (size_t)(b*NH + hh)*DH*Nn
                    : d_k + (size_t)(b*NH + hh)*DH*Lpad;
                int t0 = tok + ((sec == 0) ? 0 : NKV);
                base[(size_t)dd*rl + t0]         = acc4[0]*mult;
                base[(size_t)(dd+1)*rl + t0]     = acc4[1]*mult;
                base[(size_t)dd*rl + t0 + 8]     = acc4[2]*mult;
                base[(size_t)(dd+1)*rl + t0 + 8] = acc4[3]*mult;
            }
        }
    }
}

// ------------------------- output projection GEMM (mma.sync bf16x3) -------------------------
__global__ __launch_bounds__(256, 1) void out_mma_kernel(const float* __restrict__ bout) {
    extern __shared__ __align__(16) char smem[];
    int b = blockIdx.z, m0 = blockIdx.x * 128, n0 = blockIdx.y * 128;

    float acc[4][4][4];
#pragma unroll
    for (int i = 0; i < 4; i++)
#pragma unroll
        for (int j = 0; j < 4; j++)
#pragma unroll
            for (int r = 0; r < 4; r++) acc[i][j][r] = 0.f;

    gemm_bf16x3_acc(d_ohi + ((size_t)b*Nn + m0)*HID, d_olo + ((size_t)b*Nn + m0)*HID,
                    d_wohi + (size_t)n0*HID,         d_wolo + (size_t)n0*HID,
                    smem, acc);

    const int tid = threadIdx.x, w = tid >> 5, l = tid & 31;
    const int mb = (w >> 2) * 64, nb = (w & 3) * 32;
    const int trow = l >> 2, tcol = (l & 3) * 2;

#pragma unroll
    for (int mt = 0; mt < 4; mt++) {
#pragma unroll
        for (int nt = 0; nt < 4; nt++) {
            int tok = m0 + mb + mt*16 + trow;
            int cc  = n0 + nb + nt*8 + tcol;
            float b0 = bout[cc], b1 = bout[cc+1];
            float* acc4 = acc[mt][nt];
            d_y[((size_t)b*Cc + cc)*Nn + tok]       = acc4[0] + b0;
            d_y[((size_t)b*Cc + cc+1)*Nn + tok]     = acc4[1] + b1;
            d_y[((size_t)b*Cc + cc)*Nn + tok + 8]   = acc4[2] + b0;
            d_y[((size_t)b*Cc + cc+1)*Nn + tok + 8] = acc4[3] + b1;
        }
    }
}

// ------------------------- Flash attention (128q x 128k tiles, 8x8, FFMA2) -------------------------
__global__ __launch_bounds__(256, 1) void flash_kernel() {
    extern __shared__ __align__(16) float sm[];
    float* Qs = sm;                 // [64][128]  swizzled cols  (k=d major)
    float* Ks = sm + 8192;          // [64][128]  swizzled cols
    float* Vs = sm + 16384;         // [128][68]
    float* Ps = sm + 25088;         // [128][128] swizzled cols
    int qt = blockIdx.x, h = blockIdx.y, b = blockIdx.z;
    int tid = threadIdx.x, ty = tid >> 4, tx = tid & 15;
    const float* qg = d_q + (size_t)(b*NH + h)*DH*Nn + qt*KT;
    const float* kg = d_k + (size_t)(b*NH + h)*DH*Lpad;
    const float* vg = d_v + (size_t)(b*NH + h)*Lpad*DH;

    const int oA0 = SWZ(ty*8), oA1 = SWZ(ty*8+4);
    const int oB0 = SWZ(tx*8), oB1 = SWZ(tx*8+4);

#pragma unroll
    for (int i = 0; i < 8; i++) {
        int idx = tid + i*256;
        int d = idx >> 5, c4 = (idx & 31) << 2;
        *(float4*)&Qs[d*128 + SWZ(c4)] = *(const float4*)(qg + (size_t)d*Nn + c4);
    }

    float m[8], l[8];
    u64 o2[8][2];
#pragma unroll
    for (int i = 0; i < 8; i++) {
        m[i] = -1e30f; l[i] = 0.f;
        o2[i][0] = 0ULL; o2[i][1] = 0ULL;
    }

    for (int kt = 0; kt < NKT; kt++) {
#pragma unroll
        for (int i = 0; i < 8; i++) {
            int idx = tid + i*256;
            int d = idx >> 5, c4 = (idx & 31) << 2;
            *(float4*)&Ks[d*128 + SWZ(c4)] =
                *(const float4*)(kg + (size_t)d*Lpad + kt*KT + c4);
        }
#pragma unroll
        for (int i = 0; i < 8; i++) {
            int idx = tid + i*256;
            int r = idx >> 4, c4 = (idx & 15) << 2;
            *(float4*)&Vs[r*68 + c4] =
                *(const float4*)(vg + (size_t)(kt*KT + r)*DH + c4);
        }
        __syncthreads();

        u64 s2[8][4];
#pragma unroll
        for (int i = 0; i < 8; i++)
#pragma unroll
            for (int j = 0; j < 4; j++) s2[i][j] = 0ULL;

#pragma unroll 4
        for (int kk = 0; kk < 64; kk++) {
            float a[8];
            *(float4*)a      = *(const float4*)&Qs[kk*128 + oA0];
            *(float4*)(a+4)  = *(const float4*)&Qs[kk*128 + oA1];
            ulonglong2 b0 = *(const ulonglong2*)&Ks[kk*128 + oB0];
            ulonglong2 b1 = *(const ulonglong2*)&Ks[kk*128 + oB1];
#pragma unroll
            for (int i = 0; i < 8; i++) {
                u64 ad = dupf(a[i]);
                fma2(s2[i][0], ad, b0.x);
                fma2(s2[i][1], ad, b0.y);
                fma2(s2[i][2], ad, b1.x);
                fma2(s2[i][3], ad, b1.y);
            }
        }

        float s[8][8];
#pragma unroll
        for (int i = 0; i < 8; i++) {
#pragma unroll
            for (int j2 = 0; j2 < 4; j2++) {
                float2 c = unpk(s2[i][j2]);
                s[i][j2*2] = c.x; s[i][j2*2+1] = c.y;
            }
        }

        if (kt == NKT-1) {
#pragma unroll
            for (int jj = 0; jj < 8; jj++)
                if ((NKT-1)*KT + tx*8 + jj >= Ltot)
#pragma unroll
                    for (int i = 0; i < 8; i++) s[i][jj] = -1e30f;
        }

#pragma unroll
        for (int i = 0; i < 8; i++) {
            float rm = s[i][0];
#pragma unroll
            for (int jj = 1; jj < 8; jj++) rm = fmaxf(rm, s[i][jj]);
#pragma unroll
            for (int off = 8; off; off >>= 1)
                rm = fmaxf(rm, __shfl_xor_sync(~0u, rm, off, 16));
            float mn = fmaxf(m[i], rm);
            float alpha = __expf(m[i] - mn);
            m[i] = mn;
            float rs = 0.f;
#pragma unroll
            for (int jj = 0; jj < 8; jj++) { s[i][jj] = __expf(s[i][jj] - mn); rs += s[i][jj]; }
#pragma unroll
            for (int off = 8; off; off >>= 1)
                rs += __shfl_xor_sync(~0u, rs, off, 16);
            l[i] = l[i]*alpha + rs;
            u64 ad = dupf(alpha);
            mul2(o2[i][0], ad); mul2(o2[i][1], ad);
            float4 p0, p1;
            p0.x = s[i][0]; p0.y = s[i][1]; p0.z = s[i][2]; p0.w = s[i][3];
            p1.x = s[i][4]; p1.y = s[i][5]; p1.z = s[i][6]; p1.w = s[i][7];
            *(float4*)&Ps[(ty*8+i)*128 + oB0] = p0;
            *(float4*)&Ps[(ty*8+i)*128 + oB1] = p1;
        }
        __syncthreads();

#pragma unroll 4
        for (int j0 = 0; j0 < 128; j0 += 4) {
            ulonglong2 v0 = *(const ulonglong2*)&Vs[(j0+0)*68 + tx*4];
            ulonglong2 v1 = *(const ulonglong2*)&Vs[(j0+1)*68 + tx*4];
            ulonglong2 v2 = *(const ulonglong2*)&Vs[(j0+2)*68 + tx*4];
            ulonglong2 v3 = *(const ulonglong2*)&Vs[(j0+3)*68 + tx*4];
            int po = SWZ(j0);
#pragma unroll
            for (int ii = 0; ii < 8; ii++) {
                float4 p = *(const float4*)&Ps[(ty*8+ii)*128 + po];
                u64 px = dupf(p.x), py = dupf(p.y), pz = dupf(p.z), pw = dupf(p.w);
                fma2(o2[ii][0], px, v0.x); fma2(o2[ii][1], px, v0.y);
                fma2(o2[ii][0], py, v1.x); fma2(o2[ii][1], py, v1.y);
                fma2(o2[ii][0], pz, v2.x); fma2(o2[ii][1], pz, v2.y);
                fma2(o2[ii][0], pw, v3.x); fma2(o2[ii][1], pw, v3.y);
            }
        }
        __syncthreads();
    }

    // epilogue: write bf16 hi/lo for the tensor-core out projection
    size_t eb = ((size_t)b*Nn + qt*KT)*HID + (size_t)h*DH + tx*4;
#pragma unroll
    for (int i = 0; i < 8; i++) {
        float inv = 1.f / l[i];
        float2 c0 = unpk(o2[i][0]), c1 = unpk(o2[i][1]);
        float f[4] = {c0.x*inv, c0.y*inv, c1.x*inv, c1.y*inv};
        size_t idx = eb + (size_t)(ty*8+i)*HID;
        __nv_bfloat162 h0, h1, l0, l1;
        h0.x = __float2bfloat16(f[0]); h0.y = __float2bfloat16(f[1]);
        h1.x = __float2bfloat16(f[2]); h1.y = __float2bfloat16(f[3]);
        l0.x = __float2bfloat16(f[0] - __bfloat162float(h0.x));
        l0.y = __float2bfloat16(f[1] - __bfloat162float(h0.y));
        l1.x = __float2bfloat16(f[2] - __bfloat162float(h1.x));
        l1.y = __float2bfloat16(f[3] - __bfloat162float(h1.y));
        *(__nv_bfloat162*)(d_ohi + idx)     = h0;
        *(__nv_bfloat162*)(d_ohi + idx + 2) = h1;
        *(__nv_bfloat162*)(d_olo + idx)     = l0;
        *(__nv_bfloat162*)(d_olo + idx + 2) = l1;
    }
}

// ------------------------- GN2 apply -> final output -------------------------
__global__ void gn_apply_kernel(float* __restrict__ out) {
    int f = blockIdx.x * 256 + threadIdx.x;   // float4 index over B*C*N
    float4 v = ((const float4*)d_y)[f];
    int bc = f / (Nn/4);
    float s = d_s2[bc], bb = d_b2[bc];
    float4 r;
    r.x = v.x*s + bb; r.y = v.y*s + bb; r.z = v.z*s + bb; r.w = v.w*s + bb;
    ((float4*)out)[f] = r;
}

// ------------------------- launch -------------------------
extern "C" void kernel_launch(void* const* d_in, const int* in_sizes, int n_in,
                              void* d_out, int out_size) {
    const float* x     = (const float*)d_in[0];
    const float* gn1_w = (const float*)d_in[1];
    const float* gn1_b = (const float*)d_in[2];
    const float* w_qkv = (const float*)d_in[3];
    const float* memkv = (const float*)d_in[4];
    const float* w_out = (const float*)d_in[5];
    const float* b_out = (const float*)d_in[6];
    const float* gn2_w = (const float*)d_in[7];
    const float* gn2_b = (const float*)d_in[8];
    float* out = (float*)d_out;

    const int FLASH_SMEM = (8192 + 8192 + 128*68 + 128*128) * 4;  // 165888 B
    const int GEMM_SMEM  = 65536;

    static bool attr_set = false;
    if (!attr_set) {
        cudaFuncSetAttribute(flash_kernel,   cudaFuncAttributeMaxDynamicSharedMemorySize, FLASH_SMEM);
        cudaFuncSetAttribute(qkv_mma_kernel, cudaFuncAttributeMaxDynamicSharedMemorySize, GEMM_SMEM);
        cudaFuncSetAttribute(out_mma_kernel, cudaFuncAttributeMaxDynamicSharedMemorySize, GEMM_SMEM);
        attr_set = true;
    }

    float *p_s1, *p_b1, *p_s2, *p_b2, *p_y;
    cudaGetSymbolAddress((void**)&p_s1, d_s1);
    cudaGetSymbolAddress((void**)&p_b1, d_b1);
    cudaGetSymbolAddress((void**)&p_s2, d_s2);
    cudaGetSymbolAddress((void**)&p_b2, d_b2);
    cudaGetSymbolAddress((void**)&p_y, d_y);
    bf16 *p_whi, *p_wlo, *p_wohi, *p_wolo;
    cudaGetSymbolAddress((void**)&p_whi,  d_whi);
    cudaGetSymbolAddress((void**)&p_wlo,  d_wlo);
    cudaGetSymbolAddress((void**)&p_wohi, d_wohi);
    cudaGetSymbolAddress((void**)&p_wolo, d_wolo);

    gn_stats_kernel<<<Bb*Gg, 256>>>(x, gn1_w, gn1_b, p_s1, p_b1);
    prep_x_kernel<<<dim3(Nn/32, Cc/32, Bb), 256>>>(x);
    split_kernel<<<(QKVJ*Cc)/256, 256>>>(w_qkv, p_whi, p_wlo);
    split_kernel<<<(Cc*HID)/256, 256>>>(w_out, p_wohi, p_wolo);
    fill_memkv_kernel<<<Bb*NH, 256>>>(memkv);
    qkv_mma_kernel<<<dim3(Nn/128, QKVJ/128, Bb), 256, GEMM_SMEM>>>();
    flash_kernel<<<dim3(Nn/KT, NH, Bb), 256, FLASH_SMEM>>>();
    out_mma_kernel<<<dim3(Nn/128, HID/128, Bb), 256, GEMM_SMEM>>>(b_out);
    gn_stats_kernel<<<Bb*Gg, 256>>>(p_y, gn2_w, gn2_b, p_s2, p_b2);
    gn_apply_kernel<<<(Bb*Cc*Nn/4)/256, 256>>>(out);
}

// round 7
// speedup vs baseline: 3.3459x; 1.6066x over previous
#include <cuda_runtime.h>
#include <cuda_bf16.h>
#include <cstdint>

#define Bb   2
#define Cc   512
#define Nn   2304          // 48*48
#define Gg   32
#define CG   16            // Cc/Gg
#define NH   8
#define DH   64
#define HID  512
#define QKVJ 1536
#define NKV  4
#define Ltot 2308          // Nn + NKV
#define Lpad 2432          // 19*128
#define KT   128
#define NKT  19
#define SCALE 0.125f       // DH^-0.5

typedef unsigned long long u64;
typedef __nv_bfloat16 bf16;

// byte swizzle for 128-byte rows (mma smem tiles)
#define SW128B(o) ((o) ^ (((o) >> 3) & 0x70))

// ---------- mma.sync helpers ----------
__device__ __forceinline__ uint32_t smem_u32_of(const void* p) {
    uint32_t a;
    asm("{ .reg .u64 t; cvta.to.shared.u64 t, %1; cvt.u32.u64 %0, t; }" : "=r"(a) : "l"(p));
    return a;
}
__device__ __forceinline__ void ldm_x4(uint32_t r[4], uint32_t a) {
    asm volatile("ldmatrix.sync.aligned.m8n8.x4.shared.b16 {%0,%1,%2,%3}, [%4];"
        : "=r"(r[0]), "=r"(r[1]), "=r"(r[2]), "=r"(r[3]) : "r"(a));
}
__device__ __forceinline__ void ldm_x2(uint32_t r[2], uint32_t a) {
    asm volatile("ldmatrix.sync.aligned.m8n8.x2.shared.b16 {%0,%1}, [%2];"
        : "=r"(r[0]), "=r"(r[1]) : "r"(a));
}
__device__ __forceinline__ void mma_bf16(float d[4], const uint32_t a[4], const uint32_t b[2]) {
    asm volatile(
        "mma.sync.aligned.m16n8k16.row.col.f32.bf16.bf16.f32 "
        "{%0,%1,%2,%3}, {%4,%5,%6,%7}, {%8,%9}, {%0,%1,%2,%3};"
        : "+f"(d[0]), "+f"(d[1]), "+f"(d[2]), "+f"(d[3])
        : "r"(a[0]), "r"(a[1]), "r"(a[2]), "r"(a[3]), "r"(b[0]), "r"(b[1]));
}

// pack two floats to bf16x2 hi + residual lo
__device__ __forceinline__ void split2(float a, float b, uint32_t& hi, uint32_t& lo) {
    __nv_bfloat162 h, l2;
    h.x = __float2bfloat16(a); h.y = __float2bfloat16(b);
    l2.x = __float2bfloat16(a - __bfloat162float(h.x));
    l2.y = __float2bfloat16(b - __bfloat162float(h.y));
    hi = *(uint32_t*)&h; lo = *(uint32_t*)&l2;
}

// ------------------------- scratch (device globals) -------------------------
__device__ float d_s1[Bb*Cc], d_b1[Bb*Cc], d_s2[Bb*Cc], d_b2[Bb*Cc];
__device__ bf16 d_thi[(size_t)Bb*Nn*Cc],  d_tlo[(size_t)Bb*Nn*Cc];   // tokens [b][tok][c]
__device__ bf16 d_whi[(size_t)QKVJ*Cc],   d_wlo[(size_t)QKVJ*Cc];    // w_qkv  [j][c]
__device__ bf16 d_wohi[(size_t)Cc*HID],   d_wolo[(size_t)Cc*HID];    // w_out  [c][j]
__device__ bf16 d_qhi[(size_t)Bb*NH*Nn*DH],   d_qlo[(size_t)Bb*NH*Nn*DH];    // [b,h][tok][d] prescaled
__device__ bf16 d_khi[(size_t)Bb*NH*Lpad*DH], d_klo[(size_t)Bb*NH*Lpad*DH];  // [b,h][tok][d]
__device__ bf16 d_vhi[(size_t)Bb*NH*DH*Lpad], d_vlo[(size_t)Bb*NH*DH*Lpad];  // [b,h][d][tok]
__device__ bf16 d_ohi[(size_t)Bb*Nn*HID], d_olo[(size_t)Bb*Nn*HID];  // attn out [b][tok][j]
__device__ float d_y[(size_t)Bb*Cc*Nn];

// ------------------------- GroupNorm stats -> affine -------------------------
__global__ void gn_stats_kernel(const float* __restrict__ src,
                                const float* __restrict__ w,
                                const float* __restrict__ bgn,
                                float* __restrict__ sout,
                                float* __restrict__ bout) {
    int b = blockIdx.x >> 5;
    int g = blockIdx.x & 31;
    const float* p = src + ((size_t)b*Cc + g*CG) * Nn;
    float sum = 0.f, sq = 0.f;
    for (int i = threadIdx.x; i < CG*Nn; i += 256) {
        float v = p[i]; sum += v; sq += v*v;
    }
    __shared__ float r0[8], r1[8];
    __shared__ float smu, srs;
    int lane = threadIdx.x & 31, wid = threadIdx.x >> 5;
#pragma unroll
    for (int off = 16; off; off >>= 1) {
        sum += __shfl_xor_sync(~0u, sum, off);
        sq  += __shfl_xor_sync(~0u, sq,  off);
    }
    if (!lane) { r0[wid] = sum; r1[wid] = sq; }
    __syncthreads();
    if (threadIdx.x == 0) {
        float s = 0.f, q = 0.f;
#pragma unroll
        for (int i = 0; i < 8; i++) { s += r0[i]; q += r1[i]; }
        float inv = 1.f / (float)(CG*Nn);
        float mu  = s * inv;
        float var = q * inv - mu*mu;
        smu = mu; srs = rsqrtf(var + 1e-5f);
    }
    __syncthreads();
    if (threadIdx.x < CG) {
        int c = g*CG + threadIdx.x;
        float ww = w[c];
        float sc = srs * ww;
        sout[b*Cc + c] = sc;
        bout[b*Cc + c] = bgn[c] - smu * sc;
    }
}

// ------------------------- prep: transpose x + GN1 affine + bf16 split -------------------------
__global__ void prep_x_kernel(const float* __restrict__ x) {
    __shared__ float t[32][33];
    int b = blockIdx.z;
    int c0 = blockIdx.y * 32;
    int t0 = blockIdx.x * 32;
    int lx = threadIdx.x & 31, ly = threadIdx.x >> 5;
#pragma unroll
    for (int i = 0; i < 4; i++) {
        int c = c0 + ly + i*8;
        float v = x[((size_t)b*Cc + c)*Nn + t0 + lx];
        t[ly + i*8][lx] = v * d_s1[b*Cc + c] + d_b1[b*Cc + c];
    }
    __syncthreads();
#pragma unroll
    for (int i = 0; i < 4; i++) {
        int tok = t0 + ly + i*8;
        int c = c0 + lx;
        float v = t[lx][ly + i*8];
        bf16 hi = __float2bfloat16(v);
        bf16 lo = __float2bfloat16(v - __bfloat162float(hi));
        size_t idx = ((size_t)b*Nn + tok)*Cc + c;
        d_thi[idx] = hi; d_tlo[idx] = lo;
    }
}

// ------------------------- prep: split an fp32 matrix into bf16 hi/lo -------------------------
__global__ void split_kernel(const float* __restrict__ src,
                             bf16* __restrict__ hi,
                             bf16* __restrict__ lo) {
    int i = blockIdx.x * 256 + threadIdx.x;
    float v = src[i];
    bf16 h = __float2bfloat16(v);
    hi[i] = h;
    lo[i] = __float2bfloat16(v - __bfloat162float(h));
}

// ------------------------- memory kv prepend + zero pad (bf16 hi/lo) -------------------------
__global__ void fill_memkv_kernel(const float* __restrict__ mem) {
    int h = blockIdx.x & 7, b = blockIdx.x >> 3;
    int bh = b*NH + h;
    int t = threadIdx.x;            // 256 threads == NKV*DH
    const bf16 z = __float2bfloat16(0.f);
    {
        int l = t >> 6, d = t & 63;
        float kv = mem[((size_t)h*DH + d)*NKV + l];
        float vv = mem[((size_t)(NH + h)*DH + d)*NKV + l];
        bf16 kh = __float2bfloat16(kv);
        bf16 vh = __float2bfloat16(vv);
        size_t ki = ((size_t)bh*Lpad + l)*DH + d;
        size_t vi = ((size_t)bh*DH + d)*Lpad + l;
        d_khi[ki] = kh; d_klo[ki] = __float2bfloat16(kv - __bfloat162float(kh));
        d_vhi[vi] = vh; d_vlo[vi] = __float2bfloat16(vv - __bfloat162float(vh));
    }
    const int PADT = Lpad - Ltot;   // 124
    for (int i = t; i < PADT*DH; i += 256) {
        int r = i / DH, d = i % DH;
        size_t ki = ((size_t)bh*Lpad + Ltot + r)*DH + d;
        d_khi[ki] = z; d_klo[ki] = z;
        size_t vi = ((size_t)bh*DH + d)*Lpad + Ltot + r;
        d_vhi[vi] = z; d_vlo[vi] = z;
    }
}

// ------------------------- bf16x3 mma.sync mainloop (projection GEMMs) -------------------------
#define SA_HI 0u
#define SA_LO 16384u
#define SB_HI 32768u
#define SB_LO 49152u

__device__ __forceinline__ void gemm_bf16x3_acc(
    const bf16* __restrict__ Ahi, const bf16* __restrict__ Alo,
    const bf16* __restrict__ Bhi, const bf16* __restrict__ Blo,
    char* smem, float acc[4][4][4])
{
    const int tid = threadIdx.x;
    const int w = tid >> 5, l = tid & 31;
    const int mb = (w >> 2) * 64, nb = (w & 3) * 32;
    const uint32_t sbase = smem_u32_of(smem);

    const int arow = (l & 7) + ((l >> 3) & 1) * 8;
    const int acol = (l & 16) ? 16 : 0;
    const int brow = l & 7;
    const int bcol = (l & 8) ? 16 : 0;

    const bf16* srcs[4] = {Ahi, Alo, Bhi, Blo};

    for (int ch = 0; ch < 8; ch++) {
        if (ch) __syncthreads();
        int k0 = ch * 64;
#pragma unroll
        for (int tI = 0; tI < 4; tI++) {
            const char* src = (const char*)srcs[tI] + k0*2;
            uint32_t tb = tI * 16384u;
#pragma unroll
            for (int it = 0; it < 4; it++) {
                int idx = tid + it*256;
                int row = idx >> 3, u = idx & 7;
                uint4 v = *(const uint4*)(src + (size_t)row*1024 + u*16);
                uint32_t boff = (uint32_t)row*128u + (uint32_t)u*16u;
                *(uint4*)(smem + tb + SW128B(boff)) = v;
            }
        }
        __syncthreads();

#pragma unroll
        for (int ks = 0; ks < 4; ks++) {
            int kb = ks * 32;
            uint32_t ah[4][4], al[4][4];
#pragma unroll
            for (int mt = 0; mt < 4; mt++) {
                uint32_t off = SW128B((uint32_t)(mb + mt*16 + arow)*128u + kb + acol);
                ldm_x4(ah[mt], sbase + SA_HI + off);
                ldm_x4(al[mt], sbase + SA_LO + off);
            }
            uint32_t bh[4][2], bl[4][2];
#pragma unroll
            for (int nt = 0; nt < 4; nt++) {
                uint32_t off = SW128B((uint32_t)(nb + nt*8 + brow)*128u + kb + bcol);
                ldm_x2(bh[nt], sbase + SB_HI + off);
                ldm_x2(bl[nt], sbase + SB_LO + off);
            }
#pragma unroll
            for (int mt = 0; mt < 4; mt++)
#pragma unroll
                for (int nt = 0; nt < 4; nt++) {
                    mma_bf16(acc[mt][nt], ah[mt], bh[nt]);
                    mma_bf16(acc[mt][nt], al[mt], bh[nt]);
                    mma_bf16(acc[mt][nt], ah[mt], bl[nt]);
                }
        }
    }
}

// ------------------------- QKV GEMM (mma.sync bf16x3) -> bf16 hi/lo q/k/v -------------------------
__global__ __launch_bounds__(256, 1) void qkv_mma_kernel() {
    extern __shared__ __align__(16) char smem[];
    int b = blockIdx.z, m0 = blockIdx.x * 128, n0 = blockIdx.y * 128;

    float acc[4][4][4];
#pragma unroll
    for (int i = 0; i < 4; i++)
#pragma unroll
        for (int j = 0; j < 4; j++)
#pragma unroll
            for (int r = 0; r < 4; r++) acc[i][j][r] = 0.f;

    gemm_bf16x3_acc(d_thi + ((size_t)b*Nn + m0)*Cc, d_tlo + ((size_t)b*Nn + m0)*Cc,
                    d_whi + (size_t)n0*Cc,          d_wlo + (size_t)n0*Cc,
                    smem, acc);

    const int tid = threadIdx.x, w = tid >> 5, l = tid & 31;
    const int mb = (w >> 2) * 64, nb = (w & 3) * 32;
    const int trow = l >> 2, tcol = (l & 3) * 2;
    const int sec = n0 >> 9;     // 0=q 1=k 2=v
    const float mult = (sec == 0) ? SCALE : 1.f;

#pragma unroll
    for (int mt = 0; mt < 4; mt++) {
#pragma unroll
        for (int nt = 0; nt < 4; nt++) {
            int tok = m0 + mb + mt*16 + trow;
            int j   = n0 + nb + nt*8 + tcol;
            int jl  = j & 511;
            int hh  = jl >> 6, dd = jl & 63;
            int bh  = b*NH + hh;
            float* a4 = acc[mt][nt];
            if (sec == 2) {
                // V: [d][tok]
#pragma unroll
                for (int e = 0; e < 4; e++) {
                    float v = a4[e];
                    int ddx = dd + (e & 1);
                    int tk  = NKV + tok + (e >> 1)*8;
                    bf16 h = __float2bfloat16(v);
                    size_t idx = ((size_t)bh*DH + ddx)*Lpad + tk;
                    d_vhi[idx] = h;
                    d_vlo[idx] = __float2bfloat16(v - __bfloat162float(h));
                }
            } else {
                bf16* ahp; bf16* alp; size_t ridx0, ridx1;
                if (sec == 0) {
                    ahp = d_qhi; alp = d_qlo;
                    ridx0 = ((size_t)bh*Nn + tok)*DH + dd;
                    ridx1 = ((size_t)bh*Nn + tok + 8)*DH + dd;
                } else {
                    ahp = d_khi; alp = d_klo;
                    ridx0 = ((size_t)bh*Lpad + NKV + tok)*DH + dd;
                    ridx1 = ((size_t)bh*Lpad + NKV + tok + 8)*DH + dd;
                }
                uint32_t h32, l32;
                split2(a4[0]*mult, a4[1]*mult, h32, l32);
                *(uint32_t*)(ahp + ridx0) = h32;
                *(uint32_t*)(alp + ridx0) = l32;
                split2(a4[2]*mult, a4[3]*mult, h32, l32);
                *(uint32_t*)(ahp + ridx1) = h32;
                *(uint32_t*)(alp + ridx1) = l32;
            }
        }
    }
}

// ------------------------- output projection GEMM (mma.sync bf16x3) -------------------------
__global__ __launch_bounds__(256, 1) void out_mma_kernel(const float* __restrict__ bout) {
    extern __shared__ __align__(16) char smem[];
    int b = blockIdx.z, m0 = blockIdx.x * 128, n0 = blockIdx.y * 128;

    float acc[4][4][4];
#pragma unroll
    for (int i = 0; i < 4; i++)
#pragma unroll
        for (int j = 0; j < 4; j++)
#pragma unroll
            for (int r = 0; r < 4; r++) acc[i][j][r] = 0.f;

    gemm_bf16x3_acc(d_ohi + ((size_t)b*Nn + m0)*HID, d_olo + ((size_t)b*Nn + m0)*HID,
                    d_wohi + (size_t)n0*HID,         d_wolo + (size_t)n0*HID,
                    smem, acc);

    const int tid = threadIdx.x, w = tid >> 5, l = tid & 31;
    const int mb = (w >> 2) * 64, nb = (w & 3) * 32;
    const int trow = l >> 2, tcol = (l & 3) * 2;

#pragma unroll
    for (int mt = 0; mt < 4; mt++) {
#pragma unroll
        for (int nt = 0; nt < 4; nt++) {
            int tok = m0 + mb + mt*16 + trow;
            int cc  = n0 + nb + nt*8 + tcol;
            float b0 = bout[cc], b1 = bout[cc+1];
            float* a4 = acc[mt][nt];
            d_y[((size_t)b*Cc + cc)*Nn + tok]       = a4[0] + b0;
            d_y[((size_t)b*Cc + cc+1)*Nn + tok]     = a4[1] + b1;
            d_y[((size_t)b*Cc + cc)*Nn + tok + 8]   = a4[2] + b0;
            d_y[((size_t)b*Cc + cc+1)*Nn + tok + 8] = a4[3] + b1;
        }
    }
}

// ------------------------- Flash attention (mma.sync, all proven fragment paths) -------------------------
// smem bytes: KH 0 | KL 16K | VH 32K (2 halves x 8K) | VL 48K | PH 64K (2 x 16K) | PL 96K | QH 128K | QL 144K
#define FLASH_SMEM_BYTES 163840

__global__ __launch_bounds__(256, 1) void flash_mma_kernel() {
    extern __shared__ __align__(16) char smem[];
    const uint32_t sb = smem_u32_of(smem);
    const int qt = blockIdx.x, h = blockIdx.y, b = blockIdx.z;
    const int bh = b*NH + h;
    const int tid = threadIdx.x, w = tid >> 5, l = tid & 31;
    const int trow = l >> 2, tcol = (l & 3) * 2;

    const uint32_t KH = 0u,      KL = 16384u;
    const uint32_t VH = 32768u,  VL = 49152u;
    const uint32_t PH = 65536u,  PL = 98304u;
    const uint32_t QH = 131072u, QL = 147456u;

    // ---- load Q to smem (plain) ----
    const bf16* qh_g = d_qhi + ((size_t)bh*Nn + qt*KT)*DH;
    const bf16* ql_g = d_qlo + ((size_t)bh*Nn + qt*KT)*DH;
#pragma unroll
    for (int i = 0; i < 4; i++) {
        int idx = tid + i*256;
        int row = idx >> 3, u = idx & 7;
        uint32_t so = SW128B((uint32_t)row*128u + (uint32_t)u*16u);
        *(uint4*)(smem + QH + so) = *(const uint4*)(qh_g + (size_t)row*DH + u*8);
        *(uint4*)(smem + QL + so) = *(const uint4*)(ql_g + (size_t)row*DH + u*8);
    }
    __syncthreads();

    // ---- Q fragments (proven A-path; rows w*16..w*16+15) ----
    const int arow = (l & 7) + ((l >> 3) & 1) * 8;
    const int acol = (l & 16) ? 16 : 0;
    const int brow = l & 7;
    const int bcol = (l & 8) ? 16 : 0;
    uint32_t qfh[4][4], qfl[4][4];
#pragma unroll
    for (int ks = 0; ks < 4; ks++) {
        uint32_t off = SW128B((uint32_t)(w*16 + arow)*128u + ks*32 + acol);
        ldm_x4(qfh[ks], sb + QH + off);
        ldm_x4(qfl[ks], sb + QL + off);
    }

    float mrow[2] = {-1e30f, -1e30f};
    float lrow[2] = {0.f, 0.f};
    float oacc[8][4];
#pragma unroll
    for (int nt = 0; nt < 8; nt++)
#pragma unroll
        for (int r = 0; r < 4; r++) oacc[nt][r] = 0.f;

    for (int kt = 0; kt < NKT; kt++) {
        __syncthreads();   // all warps done reading prev K/V/P

        // ---- load K [128 tok][64 d] ----
        const bf16* kh_g = d_khi + ((size_t)bh*Lpad + kt*KT)*DH;
        const bf16* kl_g = d_klo + ((size_t)bh*Lpad + kt*KT)*DH;
#pragma unroll
        for (int i = 0; i < 4; i++) {
            int idx = tid + i*256;
            int row = idx >> 3, u = idx & 7;
            uint32_t so = SW128B((uint32_t)row*128u + (uint32_t)u*16u);
            *(uint4*)(smem + KH + so) = *(const uint4*)(kh_g + (size_t)row*DH + u*8);
            *(uint4*)(smem + KL + so) = *(const uint4*)(kl_g + (size_t)row*DH + u*8);
        }
        // ---- load V [2 half][64 d][64 tok] ----
        const bf16* vh_g = d_vhi + (size_t)bh*DH*Lpad + kt*KT;
        const bf16* vl_g = d_vlo + (size_t)bh*DH*Lpad + kt*KT;
#pragma unroll
        for (int i = 0; i < 4; i++) {
            int idx = tid + i*256;
            int dd = idx >> 4, c = idx & 15;
            int hf = c >> 3, u = c & 7;
            uint32_t so = (uint32_t)hf*8192u + SW128B((uint32_t)dd*128u + (uint32_t)u*16u);
            size_t g = (size_t)dd*Lpad + hf*64 + u*8;
            *(uint4*)(smem + VH + so) = *(const uint4*)(vh_g + g);
            *(uint4*)(smem + VL + so) = *(const uint4*)(vl_g + g);
        }
        __syncthreads();

        // ---- S = Q K^T (proven B-path, ldm_x2 per n-tile) ----
        float sacc[16][4];
#pragma unroll
        for (int nt = 0; nt < 16; nt++)
#pragma unroll
            for (int r = 0; r < 4; r++) sacc[nt][r] = 0.f;

#pragma unroll
        for (int ks = 0; ks < 4; ks++) {
#pragma unroll
            for (int nt = 0; nt < 16; nt++) {
                uint32_t off = SW128B((uint32_t)(nt*8 + brow)*128u + ks*32 + bcol);
                uint32_t kh2[2], kl2[2];
                ldm_x2(kh2, sb + KH + off);
                ldm_x2(kl2, sb + KL + off);
                mma_bf16(sacc[nt], qfh[ks], kh2);
                mma_bf16(sacc[nt], qfl[ks], kh2);
                mma_bf16(sacc[nt], qfh[ks], kl2);
            }
        }

        // ---- mask tail tile ----
        if (kt == NKT - 1) {
#pragma unroll
            for (int nt = 0; nt < 16; nt++) {
                int k0i = kt*KT + nt*8 + tcol;
                if (k0i >= Ltot)     { sacc[nt][0] = -1e30f; sacc[nt][2] = -1e30f; }
                if (k0i + 1 >= Ltot) { sacc[nt][1] = -1e30f; sacc[nt][3] = -1e30f; }
            }
        }

        // ---- online softmax (rows trow, trow+8; quad-shfl reduce) ----
#pragma unroll
        for (int r = 0; r < 2; r++) {
            int ro = 2*r;
            float rm = -1e30f;
#pragma unroll
            for (int nt = 0; nt < 16; nt++)
                rm = fmaxf(rm, fmaxf(sacc[nt][ro], sacc[nt][ro+1]));
            rm = fmaxf(rm, __shfl_xor_sync(~0u, rm, 1, 4));
            rm = fmaxf(rm, __shfl_xor_sync(~0u, rm, 2, 4));
            float mn = fmaxf(mrow[r], rm);
            float alpha = __expf(mrow[r] - mn);
            mrow[r] = mn;
            float rs = 0.f;
#pragma unroll
            for (int nt = 0; nt < 16; nt++) {
                float p0 = __expf(sacc[nt][ro]   - mn);
                float p1 = __expf(sacc[nt][ro+1] - mn);
                sacc[nt][ro] = p0; sacc[nt][ro+1] = p1;
                rs += p0 + p1;
            }
            rs += __shfl_xor_sync(~0u, rs, 1, 4);
            rs += __shfl_xor_sync(~0u, rs, 2, 4);
            lrow[r] = lrow[r]*alpha + rs;
#pragma unroll
            for (int nt = 0; nt < 8; nt++) {
                oacc[nt][ro] *= alpha; oacc[nt][ro+1] *= alpha;
            }
        }

        // ---- write P hi/lo to smem [2 half][128 q][64 tok] (each warp writes only its rows) ----
#pragma unroll
        for (int nt = 0; nt < 16; nt++) {
            int col = nt*8 + tcol;
            uint32_t hf = (uint32_t)(col >> 6) * 16384u;
            uint32_t bc = (uint32_t)(col & 63) * 2u;
            uint32_t h32, l32;
            split2(sacc[nt][0], sacc[nt][1], h32, l32);
            uint32_t o0 = hf + SW128B((uint32_t)(w*16 + trow)*128u + bc);
            *(uint32_t*)(smem + PH + o0) = h32;
            *(uint32_t*)(smem + PL + o0) = l32;
            split2(sacc[nt][2], sacc[nt][3], h32, l32);
            uint32_t o1 = hf + SW128B((uint32_t)(w*16 + trow + 8)*128u + bc);
            *(uint32_t*)(smem + PH + o1) = h32;
            *(uint32_t*)(smem + PL + o1) = l32;
        }
        __syncwarp();   // P rows are warp-private: warp-level ordering suffices

        // ---- O += P V (proven A-path for P, proven B-path for V) ----
#pragma unroll
        for (int ks2 = 0; ks2 < 8; ks2++) {
            uint32_t hfA = (uint32_t)(ks2 >> 2) * 16384u;
            uint32_t hfB = (uint32_t)(ks2 >> 2) * 8192u;
            uint32_t kb  = (uint32_t)(ks2 & 3) * 32u;
            uint32_t pfh[4], pfl[4];
            uint32_t offA = hfA + SW128B((uint32_t)(w*16 + arow)*128u + kb + acol);
            ldm_x4(pfh, sb + PH + offA);
            ldm_x4(pfl, sb + PL + offA);
#pragma unroll
            for (int nt = 0; nt < 8; nt++) {
                uint32_t offB = hfB + SW128B((uint32_t)(nt*8 + brow)*128u + kb + bcol);
                uint32_t vh2[2], vl2[2];
                ldm_x2(vh2, sb + VH + offB);
                ldm_x2(vl2, sb + VL + offB);
                mma_bf16(oacc[nt], pfh, vh2);
                mma_bf16(oacc[nt], pfl, vh2);
                mma_bf16(oacc[nt], pfh, vl2);
            }
        }
    }

    // ---- epilogue: O/l -> bf16 hi/lo [tok][HID] ----
#pragma unroll
    for (int r = 0; r < 2; r++) {
        float inv = 1.f / lrow[r];
        int tok = qt*KT + w*16 + trow + r*8;
        size_t rowb = (size_t)(b*Nn + tok)*HID + h*DH;
#pragma unroll
        for (int nt = 0; nt < 8; nt++) {
            uint32_t h32, l32;
            split2(oacc[nt][2*r]*inv, oacc[nt][2*r+1]*inv, h32, l32);
            int col = nt*8 + tcol;
            *(uint32_t*)(d_ohi + rowb + col) = h32;
            *(uint32_t*)(d_olo + rowb + col) = l32;
        }
    }
}

// ------------------------- GN2 apply -> final output -------------------------
__global__ void gn_apply_kernel(float* __restrict__ out) {
    int f = blockIdx.x * 256 + threadIdx.x;
    float4 v = ((const float4*)d_y)[f];
    int bc = f / (Nn/4);
    float s = d_s2[bc], bb = d_b2[bc];
    float4 r;
    r.x = v.x*s + bb; r.y = v.y*s + bb; r.z = v.z*s + bb; r.w = v.w*s + bb;
    ((float4*)out)[f] = r;
}

// ------------------------- launch -------------------------
extern "C" void kernel_launch(void* const* d_in, const int* in_sizes, int n_in,
                              void* d_out, int out_size) {
    const float* x     = (const float*)d_in[0];
    const float* gn1_w = (const float*)d_in[1];
    const float* gn1_b = (const float*)d_in[2];
    const float* w_qkv = (const float*)d_in[3];
    const float* memkv = (const float*)d_in[4];
    const float* w_out = (const float*)d_in[5];
    const float* b_out = (const float*)d_in[6];
    const float* gn2_w = (const float*)d_in[7];
    const float* gn2_b = (const float*)d_in[8];
    float* out = (float*)d_out;

    const int GEMM_SMEM = 65536;

    static bool attr_set = false;
    if (!attr_set) {
        cudaFuncSetAttribute(flash_mma_kernel, cudaFuncAttributeMaxDynamicSharedMemorySize, FLASH_SMEM_BYTES);
        cudaFuncSetAttribute(qkv_mma_kernel,   cudaFuncAttributeMaxDynamicSharedMemorySize, GEMM_SMEM);
        cudaFuncSetAttribute(out_mma_kernel,   cudaFuncAttributeMaxDynamicSharedMemorySize, GEMM_SMEM);
        attr_set = true;
    }

    float *p_s1, *p_b1, *p_s2, *p_b2, *p_y;
    cudaGetSymbolAddress((void**)&p_s1, d_s1);
    cudaGetSymbolAddress((void**)&p_b1, d_b1);
    cudaGetSymbolAddress((void**)&p_s2, d_s2);
    cudaGetSymbolAddress((void**)&p_b2, d_b2);
    cudaGetSymbolAddress((void**)&p_y, d_y);
    bf16 *p_whi, *p_wlo, *p_wohi, *p_wolo;
    cudaGetSymbolAddress((void**)&p_whi,  d_whi);
    cudaGetSymbolAddress((void**)&p_wlo,  d_wlo);
    cudaGetSymbolAddress((void**)&p_wohi, d_wohi);
    cudaGetSymbolAddress((void**)&p_wolo, d_wolo);

    gn_stats_kernel<<<Bb*Gg, 256>>>(x, gn1_w, gn1_b, p_s1, p_b1);
    prep_x_kernel<<<dim3(Nn/32, Cc/32, Bb), 256>>>(x);
    split_kernel<<<(QKVJ*Cc)/256, 256>>>(w_qkv, p_whi, p_wlo);
    split_kernel<<<(Cc*HID)/256, 256>>>(w_out, p_wohi, p_wolo);
    fill_memkv_kernel<<<Bb*NH, 256>>>(memkv);
    qkv_mma_kernel<<<dim3(Nn/128, QKVJ/128, Bb), 256, GEMM_SMEM>>>();
    flash_mma_kernel<<<dim3(Nn/KT, NH, Bb), 256, FLASH_SMEM_BYTES>>>();
    out_mma_kernel<<<dim3(Nn/128, HID/128, Bb), 256, GEMM_SMEM>>>(b_out);
    gn_stats_kernel<<<Bb*Gg, 256>>>(p_y, gn2_w, gn2_b, p_s2, p_b2);
    gn_apply_kernel<<<(Bb*Cc*Nn/4)/256, 256>>>(out);
}

// round 8
// speedup vs baseline: 3.6959x; 1.1046x over previous
#include <cuda_runtime.h>
#include <cuda_bf16.h>
#include <cstdint>

#define Bb   2
#define Cc   512
#define Nn   2304          // 48*48
#define Gg   32
#define CG   16            // Cc/Gg
#define NH   8
#define DH   64
#define HID  512
#define QKVJ 1536
#define NKV  4
#define Ltot 2308          // Nn + NKV
#define Lpad 2432          // 19*128
#define KT   128
#define NKT  19
#define SCALE 0.125f       // DH^-0.5

typedef unsigned long long u64;
typedef __nv_bfloat16 bf16;

// byte swizzle for 128-byte rows (mma smem tiles)
#define SW128B(o) ((o) ^ (((o) >> 3) & 0x70))

// ---------- mma.sync helpers ----------
__device__ __forceinline__ uint32_t smem_u32_of(const void* p) {
    uint32_t a;
    asm("{ .reg .u64 t; cvta.to.shared.u64 t, %1; cvt.u32.u64 %0, t; }" : "=r"(a) : "l"(p));
    return a;
}
__device__ __forceinline__ void ldm_x4(uint32_t r[4], uint32_t a) {
    asm volatile("ldmatrix.sync.aligned.m8n8.x4.shared.b16 {%0,%1,%2,%3}, [%4];"
        : "=r"(r[0]), "=r"(r[1]), "=r"(r[2]), "=r"(r[3]) : "r"(a));
}
__device__ __forceinline__ void ldm_x2(uint32_t r[2], uint32_t a) {
    asm volatile("ldmatrix.sync.aligned.m8n8.x2.shared.b16 {%0,%1}, [%2];"
        : "=r"(r[0]), "=r"(r[1]) : "r"(a));
}
__device__ __forceinline__ void mma_bf16(float d[4], const uint32_t a[4], const uint32_t b[2]) {
    asm volatile(
        "mma.sync.aligned.m16n8k16.row.col.f32.bf16.bf16.f32 "
        "{%0,%1,%2,%3}, {%4,%5,%6,%7}, {%8,%9}, {%0,%1,%2,%3};"
        : "+f"(d[0]), "+f"(d[1]), "+f"(d[2]), "+f"(d[3])
        : "r"(a[0]), "r"(a[1]), "r"(a[2]), "r"(a[3]), "r"(b[0]), "r"(b[1]));
}
__device__ __forceinline__ void cpa16(uint32_t s, const void* g) {
    asm volatile("cp.async.cg.shared.global [%0], [%1], 16;" :: "r"(s), "l"(g));
}
#define CP_COMMIT() asm volatile("cp.async.commit_group;" ::: "memory")
#define CP_WAIT0()  asm volatile("cp.async.wait_group 0;" ::: "memory")

// pack two floats to bf16x2 hi + residual lo
__device__ __forceinline__ void split2(float a, float b, uint32_t& hi, uint32_t& lo) {
    __nv_bfloat162 h, l2;
    h.x = __float2bfloat16(a); h.y = __float2bfloat16(b);
    l2.x = __float2bfloat16(a - __bfloat162float(h.x));
    l2.y = __float2bfloat16(b - __bfloat162float(h.y));
    hi = *(uint32_t*)&h; lo = *(uint32_t*)&l2;
}

// ------------------------- scratch (device globals) -------------------------
__device__ float d_s1[Bb*Cc], d_b1[Bb*Cc], d_s2[Bb*Cc], d_b2[Bb*Cc];
__device__ bf16 d_thi[(size_t)Bb*Nn*Cc],  d_tlo[(size_t)Bb*Nn*Cc];   // tokens [b][tok][c]
__device__ bf16 d_whi[(size_t)QKVJ*Cc],   d_wlo[(size_t)QKVJ*Cc];    // w_qkv  [j][c]
__device__ bf16 d_wohi[(size_t)Cc*HID],   d_wolo[(size_t)Cc*HID];    // w_out  [c][j]
__device__ bf16 d_qhi[(size_t)Bb*NH*Nn*DH],   d_qlo[(size_t)Bb*NH*Nn*DH];    // [b,h][tok][d] prescaled
__device__ bf16 d_khi[(size_t)Bb*NH*Lpad*DH], d_klo[(size_t)Bb*NH*Lpad*DH];  // [b,h][tok][d]
__device__ bf16 d_vhi[(size_t)Bb*NH*DH*Lpad], d_vlo[(size_t)Bb*NH*DH*Lpad];  // [b,h][d][tok]
__device__ bf16 d_ohi[(size_t)Bb*Nn*HID], d_olo[(size_t)Bb*Nn*HID];  // attn out [b][tok][j]
__device__ float d_y[(size_t)Bb*Cc*Nn];

// ------------------------- GroupNorm stats -> affine -------------------------
__global__ void gn_stats_kernel(const float* __restrict__ src,
                                const float* __restrict__ w,
                                const float* __restrict__ bgn,
                                float* __restrict__ sout,
                                float* __restrict__ bout) {
    int b = blockIdx.x >> 5;
    int g = blockIdx.x & 31;
    const float* p = src + ((size_t)b*Cc + g*CG) * Nn;
    float sum = 0.f, sq = 0.f;
    for (int i = threadIdx.x; i < CG*Nn; i += 256) {
        float v = p[i]; sum += v; sq += v*v;
    }
    __shared__ float r0[8], r1[8];
    __shared__ float smu, srs;
    int lane = threadIdx.x & 31, wid = threadIdx.x >> 5;
#pragma unroll
    for (int off = 16; off; off >>= 1) {
        sum += __shfl_xor_sync(~0u, sum, off);
        sq  += __shfl_xor_sync(~0u, sq,  off);
    }
    if (!lane) { r0[wid] = sum; r1[wid] = sq; }
    __syncthreads();
    if (threadIdx.x == 0) {
        float s = 0.f, q = 0.f;
#pragma unroll
        for (int i = 0; i < 8; i++) { s += r0[i]; q += r1[i]; }
        float inv = 1.f / (float)(CG*Nn);
        float mu  = s * inv;
        float var = q * inv - mu*mu;
        smu = mu; srs = rsqrtf(var + 1e-5f);
    }
    __syncthreads();
    if (threadIdx.x < CG) {
        int c = g*CG + threadIdx.x;
        float ww = w[c];
        float sc = srs * ww;
        sout[b*Cc + c] = sc;
        bout[b*Cc + c] = bgn[c] - smu * sc;
    }
}

// ------------------------- prep: transpose x + GN1 affine + bf16 split -------------------------
__global__ void prep_x_kernel(const float* __restrict__ x) {
    __shared__ float t[32][33];
    int b = blockIdx.z;
    int c0 = blockIdx.y * 32;
    int t0 = blockIdx.x * 32;
    int lx = threadIdx.x & 31, ly = threadIdx.x >> 5;
#pragma unroll
    for (int i = 0; i < 4; i++) {
        int c = c0 + ly + i*8;
        float v = x[((size_t)b*Cc + c)*Nn + t0 + lx];
        t[ly + i*8][lx] = v * d_s1[b*Cc + c] + d_b1[b*Cc + c];
    }
    __syncthreads();
#pragma unroll
    for (int i = 0; i < 4; i++) {
        int tok = t0 + ly + i*8;
        int c = c0 + lx;
        float v = t[lx][ly + i*8];
        bf16 hi = __float2bfloat16(v);
        bf16 lo = __float2bfloat16(v - __bfloat162float(hi));
        size_t idx = ((size_t)b*Nn + tok)*Cc + c;
        d_thi[idx] = hi; d_tlo[idx] = lo;
    }
}

// ------------------------- prep: split both weight matrices (one launch) -------------------------
#define SPLIT1_BLOCKS ((QKVJ*Cc)/256)
__global__ void split_both_kernel(const float* __restrict__ w_qkv,
                                  const float* __restrict__ w_out) {
    int blk = blockIdx.x;
    const float* src; bf16 *hi, *lo; int i;
    if (blk < SPLIT1_BLOCKS) {
        src = w_qkv; hi = d_whi; lo = d_wlo;
        i = blk * 256 + threadIdx.x;
    } else {
        src = w_out; hi = d_wohi; lo = d_wolo;
        i = (blk - SPLIT1_BLOCKS) * 256 + threadIdx.x;
    }
    float v = src[i];
    bf16 h = __float2bfloat16(v);
    hi[i] = h;
    lo[i] = __float2bfloat16(v - __bfloat162float(h));
}

// ------------------------- memory kv prepend + zero pad (bf16 hi/lo) -------------------------
__global__ void fill_memkv_kernel(const float* __restrict__ mem) {
    int h = blockIdx.x & 7, b = blockIdx.x >> 3;
    int bh = b*NH + h;
    int t = threadIdx.x;            // 256 threads == NKV*DH
    const bf16 z = __float2bfloat16(0.f);
    {
        int l = t >> 6, d = t & 63;
        float kv = mem[((size_t)h*DH + d)*NKV + l];
        float vv = mem[((size_t)(NH + h)*DH + d)*NKV + l];
        bf16 kh = __float2bfloat16(kv);
        bf16 vh = __float2bfloat16(vv);
        size_t ki = ((size_t)bh*Lpad + l)*DH + d;
        size_t vi = ((size_t)bh*DH + d)*Lpad + l;
        d_khi[ki] = kh; d_klo[ki] = __float2bfloat16(kv - __bfloat162float(kh));
        d_vhi[vi] = vh; d_vlo[vi] = __float2bfloat16(vv - __bfloat162float(vh));
    }
    const int PADT = Lpad - Ltot;   // 124
    for (int i = t; i < PADT*DH; i += 256) {
        int r = i / DH, d = i % DH;
        size_t ki = ((size_t)bh*Lpad + Ltot + r)*DH + d;
        d_khi[ki] = z; d_klo[ki] = z;
        size_t vi = ((size_t)bh*DH + d)*Lpad + Ltot + r;
        d_vhi[vi] = z; d_vlo[vi] = z;
    }
}

// ------------------------- bf16x3 mma.sync mainloop (projection GEMMs) -------------------------
#define SA_HI 0u
#define SA_LO 16384u
#define SB_HI 32768u
#define SB_LO 49152u

__device__ __forceinline__ void gemm_bf16x3_acc(
    const bf16* __restrict__ Ahi, const bf16* __restrict__ Alo,
    const bf16* __restrict__ Bhi, const bf16* __restrict__ Blo,
    char* smem, float acc[4][4][4])
{
    const int tid = threadIdx.x;
    const int w = tid >> 5, l = tid & 31;
    const int mb = (w >> 2) * 64, nb = (w & 3) * 32;
    const uint32_t sbase = smem_u32_of(smem);

    const int arow = (l & 7) + ((l >> 3) & 1) * 8;
    const int acol = (l & 16) ? 16 : 0;
    const int brow = l & 7;
    const int bcol = (l & 8) ? 16 : 0;

    const bf16* srcs[4] = {Ahi, Alo, Bhi, Blo};

    for (int ch = 0; ch < 8; ch++) {
        if (ch) __syncthreads();
        int k0 = ch * 64;
#pragma unroll
        for (int tI = 0; tI < 4; tI++) {
            const char* src = (const char*)srcs[tI] + k0*2;
            uint32_t tb = tI * 16384u;
#pragma unroll
            for (int it = 0; it < 4; it++) {
                int idx = tid + it*256;
                int row = idx >> 3, u = idx & 7;
                uint4 v = *(const uint4*)(src + (size_t)row*1024 + u*16);
                uint32_t boff = (uint32_t)row*128u + (uint32_t)u*16u;
                *(uint4*)(smem + tb + SW128B(boff)) = v;
            }
        }
        __syncthreads();

#pragma unroll
        for (int ks = 0; ks < 4; ks++) {
            int kb = ks * 32;
            uint32_t ah[4][4], al[4][4];
#pragma unroll
            for (int mt = 0; mt < 4; mt++) {
                uint32_t off = SW128B((uint32_t)(mb + mt*16 + arow)*128u + kb + acol);
                ldm_x4(ah[mt], sbase + SA_HI + off);
                ldm_x4(al[mt], sbase + SA_LO + off);
            }
            uint32_t bh[4][2], bl[4][2];
#pragma unroll
            for (int nt = 0; nt < 4; nt++) {
                uint32_t off = SW128B((uint32_t)(nb + nt*8 + brow)*128u + kb + bcol);
                ldm_x2(bh[nt], sbase + SB_HI + off);
                ldm_x2(bl[nt], sbase + SB_LO + off);
            }
#pragma unroll
            for (int mt = 0; mt < 4; mt++)
#pragma unroll
                for (int nt = 0; nt < 4; nt++) {
                    mma_bf16(acc[mt][nt], ah[mt], bh[nt]);
                    mma_bf16(acc[mt][nt], al[mt], bh[nt]);
                    mma_bf16(acc[mt][nt], ah[mt], bl[nt]);
                }
        }
    }
}

// ------------------------- QKV GEMM (mma.sync bf16x3) -> bf16 hi/lo q/k/v -------------------------
__global__ __launch_bounds__(256, 1) void qkv_mma_kernel() {
    extern __shared__ __align__(16) char smem[];
    int b = blockIdx.z, m0 = blockIdx.x * 128, n0 = blockIdx.y * 128;

    float acc[4][4][4];
#pragma unroll
    for (int i = 0; i < 4; i++)
#pragma unroll
        for (int j = 0; j < 4; j++)
#pragma unroll
            for (int r = 0; r < 4; r++) acc[i][j][r] = 0.f;

    gemm_bf16x3_acc(d_thi + ((size_t)b*Nn + m0)*Cc, d_tlo + ((size_t)b*Nn + m0)*Cc,
                    d_whi + (size_t)n0*Cc,          d_wlo + (size_t)n0*Cc,
                    smem, acc);

    const int tid = threadIdx.x, w = tid >> 5, l = tid & 31;
    const int mb = (w >> 2) * 64, nb = (w & 3) * 32;
    const int trow = l >> 2, tcol = (l & 3) * 2;
    const int sec = n0 >> 9;     // 0=q 1=k 2=v
    const float mult = (sec == 0) ? SCALE : 1.f;

#pragma unroll
    for (int mt = 0; mt < 4; mt++) {
#pragma unroll
        for (int nt = 0; nt < 4; nt++) {
            int tok = m0 + mb + mt*16 + trow;
            int j   = n0 + nb + nt*8 + tcol;
            int jl  = j & 511;
            int hh  = jl >> 6, dd = jl & 63;
            int bh  = b*NH + hh;
            float* a4 = acc[mt][nt];
            if (sec == 2) {
                // V: [d][tok]
#pragma unroll
                for (int e = 0; e < 4; e++) {
                    float v = a4[e];
                    int ddx = dd + (e & 1);
                    int tk  = NKV + tok + (e >> 1)*8;
                    bf16 h = __float2bfloat16(v);
                    size_t idx = ((size_t)bh*DH + ddx)*Lpad + tk;
                    d_vhi[idx] = h;
                    d_vlo[idx] = __float2bfloat16(v - __bfloat162float(h));
                }
            } else {
                bf16* ahp; bf16* alp; size_t ridx0, ridx1;
                if (sec == 0) {
                    ahp = d_qhi; alp = d_qlo;
                    ridx0 = ((size_t)bh*Nn + tok)*DH + dd;
                    ridx1 = ((size_t)bh*Nn + tok + 8)*DH + dd;
                } else {
                    ahp = d_khi; alp = d_klo;
                    ridx0 = ((size_t)bh*Lpad + NKV + tok)*DH + dd;
                    ridx1 = ((size_t)bh*Lpad + NKV + tok + 8)*DH + dd;
                }
                uint32_t h32, l32;
                split2(a4[0]*mult, a4[1]*mult, h32, l32);
                *(uint32_t*)(ahp + ridx0) = h32;
                *(uint32_t*)(alp + ridx0) = l32;
                split2(a4[2]*mult, a4[3]*mult, h32, l32);
                *(uint32_t*)(ahp + ridx1) = h32;
                *(uint32_t*)(alp + ridx1) = l32;
            }
        }
    }
}

// ------------------------- output projection GEMM (mma.sync bf16x3) -------------------------
__global__ __launch_bounds__(256, 1) void out_mma_kernel(const float* __restrict__ bout) {
    extern __shared__ __align__(16) char smem[];
    int b = blockIdx.z, m0 = blockIdx.x * 128, n0 = blockIdx.y * 128;

    float acc[4][4][4];
#pragma unroll
    for (int i = 0; i < 4; i++)
#pragma unroll
        for (int j = 0; j < 4; j++)
#pragma unroll
            for (int r = 0; r < 4; r++) acc[i][j][r] = 0.f;

    gemm_bf16x3_acc(d_ohi + ((size_t)b*Nn + m0)*HID, d_olo + ((size_t)b*Nn + m0)*HID,
                    d_wohi + (size_t)n0*HID,         d_wolo + (size_t)n0*HID,
                    smem, acc);

    const int tid = threadIdx.x, w = tid >> 5, l = tid & 31;
    const int mb = (w >> 2) * 64, nb = (w & 3) * 32;
    const int trow = l >> 2, tcol = (l & 3) * 2;

#pragma unroll
    for (int mt = 0; mt < 4; mt++) {
#pragma unroll
        for (int nt = 0; nt < 4; nt++) {
            int tok = m0 + mb + mt*16 + trow;
            int cc  = n0 + nb + nt*8 + tcol;
            float b0 = bout[cc], b1 = bout[cc+1];
            float* a4 = acc[mt][nt];
            d_y[((size_t)b*Cc + cc)*Nn + tok]       = a4[0] + b0;
            d_y[((size_t)b*Cc + cc+1)*Nn + tok]     = a4[1] + b1;
            d_y[((size_t)b*Cc + cc)*Nn + tok + 8]   = a4[2] + b0;
            d_y[((size_t)b*Cc + cc+1)*Nn + tok + 8] = a4[3] + b1;
        }
    }
}

// ------------------------- Flash attention (mma.sync, cp.async double-buffered K/V) -------------------------
// smem: buf0 [KH 0|KL 16K|VH 32K|VL 48K], buf1 [64K..128K), PH 128K (32K), PL 160K (32K),
//       QH 192K (16K), QL 208K (16K). total 224K.
#define FB(buf)  ((uint32_t)(buf)*65536u)
#define F_KH 0u
#define F_KL 16384u
#define F_VH 32768u
#define F_VL 49152u
#define F_PH 131072u
#define F_PL 163840u
#define F_QH 196608u
#define F_QL 212992u
#define FLASH_SMEM_BYTES 229376

// issue cp.async loads of K/V tile kt into buffer buf
__device__ __forceinline__ void flash_prefetch(char* /*unused*/, uint32_t sb, int bh, int kt, int buf, int tid) {
    const bf16* kh_g = d_khi + ((size_t)bh*Lpad + kt*KT)*DH;
    const bf16* kl_g = d_klo + ((size_t)bh*Lpad + kt*KT)*DH;
#pragma unroll
    for (int i = 0; i < 4; i++) {
        int idx = tid + i*256;
        int row = idx >> 3, u = idx & 7;
        uint32_t so = SW128B((uint32_t)row*128u + (uint32_t)u*16u);
        cpa16(sb + FB(buf) + F_KH + so, kh_g + (size_t)row*DH + u*8);
        cpa16(sb + FB(buf) + F_KL + so, kl_g + (size_t)row*DH + u*8);
    }
    const bf16* vh_g = d_vhi + (size_t)bh*DH*Lpad + kt*KT;
    const bf16* vl_g = d_vlo + (size_t)bh*DH*Lpad + kt*KT;
#pragma unroll
    for (int i = 0; i < 4; i++) {
        int idx = tid + i*256;
        int dd = idx >> 4, c = idx & 15;
        int hf = c >> 3, u = c & 7;
        uint32_t so = (uint32_t)hf*8192u + SW128B((uint32_t)dd*128u + (uint32_t)u*16u);
        size_t g = (size_t)dd*Lpad + hf*64 + u*8;
        cpa16(sb + FB(buf) + F_VH + so, vh_g + g);
        cpa16(sb + FB(buf) + F_VL + so, vl_g + g);
    }
}

__global__ __launch_bounds__(256, 1) void flash_mma_kernel() {
    extern __shared__ __align__(16) char smem[];
    const uint32_t sb = smem_u32_of(smem);
    const int qt = blockIdx.x, h = blockIdx.y, b = blockIdx.z;
    const int bh = b*NH + h;
    const int tid = threadIdx.x, w = tid >> 5, l = tid & 31;
    const int trow = l >> 2, tcol = (l & 3) * 2;

    // ---- prologue: Q + tile0 via cp.async ----
    const bf16* qh_g = d_qhi + ((size_t)bh*Nn + qt*KT)*DH;
    const bf16* ql_g = d_qlo + ((size_t)bh*Nn + qt*KT)*DH;
#pragma unroll
    for (int i = 0; i < 4; i++) {
        int idx = tid + i*256;
        int row = idx >> 3, u = idx & 7;
        uint32_t so = SW128B((uint32_t)row*128u + (uint32_t)u*16u);
        cpa16(sb + F_QH + so, qh_g + (size_t)row*DH + u*8);
        cpa16(sb + F_QL + so, ql_g + (size_t)row*DH + u*8);
    }
    flash_prefetch(smem, sb, bh, 0, 0, tid);
    CP_COMMIT();
    CP_WAIT0();
    __syncthreads();

    // ---- Q fragments (proven A-path; rows w*16..w*16+15) ----
    const int arow = (l & 7) + ((l >> 3) & 1) * 8;
    const int acol = (l & 16) ? 16 : 0;
    const int brow = l & 7;
    const int bcol = (l & 8) ? 16 : 0;
    uint32_t qfh[4][4], qfl[4][4];
#pragma unroll
    for (int ks = 0; ks < 4; ks++) {
        uint32_t off = SW128B((uint32_t)(w*16 + arow)*128u + ks*32 + acol);
        ldm_x4(qfh[ks], sb + F_QH + off);
        ldm_x4(qfl[ks], sb + F_QL + off);
    }

    float mrow[2] = {-1e30f, -1e30f};
    float lrow[2] = {0.f, 0.f};
    float oacc[8][4];
#pragma unroll
    for (int nt = 0; nt < 8; nt++)
#pragma unroll
        for (int r = 0; r < 4; r++) oacc[nt][r] = 0.f;

    for (int kt = 0; kt < NKT; kt++) {
        const int buf = kt & 1;
        // prefetch next tile into the other buffer (written only; read next iter)
        if (kt + 1 < NKT) {
            flash_prefetch(smem, sb, bh, kt + 1, buf ^ 1, tid);
            CP_COMMIT();
        }
        const uint32_t KHb = FB(buf) + F_KH, KLb = FB(buf) + F_KL;
        const uint32_t VHb = FB(buf) + F_VH, VLb = FB(buf) + F_VL;

        // ---- S = Q K^T (proven B-path, ldm_x2 per n-tile) ----
        float sacc[16][4];
#pragma unroll
        for (int nt = 0; nt < 16; nt++)
#pragma unroll
            for (int r = 0; r < 4; r++) sacc[nt][r] = 0.f;

#pragma unroll
        for (int ks = 0; ks < 4; ks++) {
#pragma unroll
            for (int nt = 0; nt < 16; nt++) {
                uint32_t off = SW128B((uint32_t)(nt*8 + brow)*128u + ks*32 + bcol);
                uint32_t kh2[2], kl2[2];
                ldm_x2(kh2, sb + KHb + off);
                ldm_x2(kl2, sb + KLb + off);
                mma_bf16(sacc[nt], qfh[ks], kh2);
                mma_bf16(sacc[nt], qfl[ks], kh2);
                mma_bf16(sacc[nt], qfh[ks], kl2);
            }
        }

        // ---- mask tail tile ----
        if (kt == NKT - 1) {
#pragma unroll
            for (int nt = 0; nt < 16; nt++) {
                int k0i = kt*KT + nt*8 + tcol;
                if (k0i >= Ltot)     { sacc[nt][0] = -1e30f; sacc[nt][2] = -1e30f; }
                if (k0i + 1 >= Ltot) { sacc[nt][1] = -1e30f; sacc[nt][3] = -1e30f; }
            }
        }

        // ---- online softmax (rows trow, trow+8; quad-shfl reduce) ----
#pragma unroll
        for (int r = 0; r < 2; r++) {
            int ro = 2*r;
            float rm = -1e30f;
#pragma unroll
            for (int nt = 0; nt < 16; nt++)
                rm = fmaxf(rm, fmaxf(sacc[nt][ro], sacc[nt][ro+1]));
            rm = fmaxf(rm, __shfl_xor_sync(~0u, rm, 1, 4));
            rm = fmaxf(rm, __shfl_xor_sync(~0u, rm, 2, 4));
            float mn = fmaxf(mrow[r], rm);
            float alpha = __expf(mrow[r] - mn);
            mrow[r] = mn;
            float rs = 0.f;
#pragma unroll
            for (int nt = 0; nt < 16; nt++) {
                float p0 = __expf(sacc[nt][ro]   - mn);
                float p1 = __expf(sacc[nt][ro+1] - mn);
                sacc[nt][ro] = p0; sacc[nt][ro+1] = p1;
                rs += p0 + p1;
            }
            rs += __shfl_xor_sync(~0u, rs, 1, 4);
            rs += __shfl_xor_sync(~0u, rs, 2, 4);
            lrow[r] = lrow[r]*alpha + rs;
#pragma unroll
            for (int nt = 0; nt < 8; nt++) {
                oacc[nt][ro] *= alpha; oacc[nt][ro+1] *= alpha;
            }
        }

        // ---- write P hi/lo to smem [2 half][128 q][64 tok] (warp-private rows) ----
#pragma unroll
        for (int nt = 0; nt < 16; nt++) {
            int col = nt*8 + tcol;
            uint32_t hf = (uint32_t)(col >> 6) * 16384u;
            uint32_t bc = (uint32_t)(col & 63) * 2u;
            uint32_t h32, l32;
            split2(sacc[nt][0], sacc[nt][1], h32, l32);
            uint32_t o0 = hf + SW128B((uint32_t)(w*16 + trow)*128u + bc);
            *(uint32_t*)(smem + F_PH + o0) = h32;
            *(uint32_t*)(smem + F_PL + o0) = l32;
            split2(sacc[nt][2], sacc[nt][3], h32, l32);
            uint32_t o1 = hf + SW128B((uint32_t)(w*16 + trow + 8)*128u + bc);
            *(uint32_t*)(smem + F_PH + o1) = h32;
            *(uint32_t*)(smem + F_PL + o1) = l32;
        }
        __syncwarp();

        // ---- O += P V (proven A-path for P, proven B-path for V) ----
#pragma unroll
        for (int ks2 = 0; ks2 < 8; ks2++) {
            uint32_t hfA = (uint32_t)(ks2 >> 2) * 16384u;
            uint32_t hfB = (uint32_t)(ks2 >> 2) * 8192u;
            uint32_t kb  = (uint32_t)(ks2 & 3) * 32u;
            uint32_t pfh[4], pfl[4];
            uint32_t offA = hfA + SW128B((uint32_t)(w*16 + arow)*128u + kb + acol);
            ldm_x4(pfh, sb + F_PH + offA);
            ldm_x4(pfl, sb + F_PL + offA);
#pragma unroll
            for (int nt = 0; nt < 8; nt++) {
                uint32_t offB = hfB + SW128B((uint32_t)(nt*8 + brow)*128u + kb + bcol);
                uint32_t vh2[2], vl2[2];
                ldm_x2(vh2, sb + VHb + offB);
                ldm_x2(vl2, sb + VLb + offB);
                mma_bf16(oacc[nt], pfh, vh2);
                mma_bf16(oacc[nt], pfl, vh2);
                mma_bf16(oacc[nt], pfh, vl2);
            }
        }

        if (kt + 1 < NKT) {
            CP_WAIT0();        // next buffer landed
            __syncthreads();   // all warps done reading current buffer + P
        }
    }

    // ---- epilogue: O/l -> bf16 hi/lo [tok][HID] ----
#pragma unroll
    for (int r = 0; r < 2; r++) {
        float inv = 1.f / lrow[r];
        int tok = qt*KT + w*16 + trow + r*8;
        size_t rowb = (size_t)(b*Nn + tok)*HID + h*DH;
#pragma unroll
        for (int nt = 0; nt < 8; nt++) {
            uint32_t h32, l32;
            split2(oacc[nt][2*r]*inv, oacc[nt][2*r+1]*inv, h32, l32);
            int col = nt*8 + tcol;
            *(uint32_t*)(d_ohi + rowb + col) = h32;
            *(uint32_t*)(d_olo + rowb + col) = l32;
        }
    }
}

// ------------------------- GN2 apply -> final output -------------------------
__global__ void gn_apply_kernel(float* __restrict__ out) {
    int f = blockIdx.x * 256 + threadIdx.x;
    float4 v = ((const float4*)d_y)[f];
    int bc = f / (Nn/4);
    float s = d_s2[bc], bb = d_b2[bc];
    float4 r;
    r.x = v.x*s + bb; r.y = v.y*s + bb; r.z = v.z*s + bb; r.w = v.w*s + bb;
    ((float4*)out)[f] = r;
}

// ------------------------- launch -------------------------
extern "C" void kernel_launch(void* const* d_in, const int* in_sizes, int n_in,
                              void* d_out, int out_size) {
    const float* x     = (const float*)d_in[0];
    const float* gn1_w = (const float*)d_in[1];
    const float* gn1_b = (const float*)d_in[2];
    const float* w_qkv = (const float*)d_in[3];
    const float* memkv = (const float*)d_in[4];
    const float* w_out = (const float*)d_in[5];
    const float* b_out = (const float*)d_in[6];
    const float* gn2_w = (const float*)d_in[7];
    const float* gn2_b = (const float*)d_in[8];
    float* out = (float*)d_out;

    const int GEMM_SMEM = 65536;

    static bool attr_set = false;
    if (!attr_set) {
        cudaFuncSetAttribute(flash_mma_kernel, cudaFuncAttributeMaxDynamicSharedMemorySize, FLASH_SMEM_BYTES);
        cudaFuncSetAttribute(qkv_mma_kernel,   cudaFuncAttributeMaxDynamicSharedMemorySize, GEMM_SMEM);
        cudaFuncSetAttribute(out_mma_kernel,   cudaFuncAttributeMaxDynamicSharedMemorySize, GEMM_SMEM);
        attr_set = true;
    }

    float *p_s1, *p_b1, *p_s2, *p_b2, *p_y;
    cudaGetSymbolAddress((void**)&p_s1, d_s1);
    cudaGetSymbolAddress((void**)&p_b1, d_b1);
    cudaGetSymbolAddress((void**)&p_s2, d_s2);
    cudaGetSymbolAddress((void**)&p_b2, d_b2);
    cudaGetSymbolAddress((void**)&p_y, d_y);

    gn_stats_kernel<<<Bb*Gg, 256>>>(x, gn1_w, gn1_b, p_s1, p_b1);
    prep_x_kernel<<<dim3(Nn/32, Cc/32, Bb), 256>>>(x);
    split_both_kernel<<<SPLIT1_BLOCKS + (Cc*HID)/256, 256>>>(w_qkv, w_out);
    fill_memkv_kernel<<<Bb*NH, 256>>>(memkv);
    qkv_mma_kernel<<<dim3(Nn/128, QKVJ/128, Bb), 256, GEMM_SMEM>>>();
    flash_mma_kernel<<<dim3(Nn/KT, NH, Bb), 256, FLASH_SMEM_BYTES>>>();
    out_mma_kernel<<<dim3(Nn/128, HID/128, Bb), 256, GEMM_SMEM>>>(b_out);
    gn_stats_kernel<<<Bb*Gg, 256>>>(p_y, gn2_w, gn2_b, p_s2, p_b2);
    gn_apply_kernel<<<(Bb*Cc*Nn/4)/256, 256>>>(out);
}

// round 9
// speedup vs baseline: 3.9663x; 1.0732x over previous
#include <cuda_runtime.h>
#include <cuda_bf16.h>
#include <cstdint>

#define Bb   2
#define Cc   512
#define Nn   2304          // 48*48
#define Gg   32
#define CG   16            // Cc/Gg
#define NH   8
#define DH   64
#define HID  512
#define QKVJ 1536
#define NKV  4
#define Ltot 2308          // Nn + NKV
#define Lpad 2432          // 19*128
#define KT   128
#define NKT  19
#define SCALE 0.125f       // DH^-0.5

typedef unsigned long long u64;
typedef __nv_bfloat16 bf16;

// byte swizzle for 128-byte rows (mma smem tiles)
#define SW128B(o) ((o) ^ (((o) >> 3) & 0x70))

// ---------- mma.sync helpers ----------
__device__ __forceinline__ uint32_t smem_u32_of(const void* p) {
    uint32_t a;
    asm("{ .reg .u64 t; cvta.to.shared.u64 t, %1; cvt.u32.u64 %0, t; }" : "=r"(a) : "l"(p));
    return a;
}
__device__ __forceinline__ void ldm_x4(uint32_t r[4], uint32_t a) {
    asm volatile("ldmatrix.sync.aligned.m8n8.x4.shared.b16 {%0,%1,%2,%3}, [%4];"
        : "=r"(r[0]), "=r"(r[1]), "=r"(r[2]), "=r"(r[3]) : "r"(a));
}
__device__ __forceinline__ void ldm_x2(uint32_t r[2], uint32_t a) {
    asm volatile("ldmatrix.sync.aligned.m8n8.x2.shared.b16 {%0,%1}, [%2];"
        : "=r"(r[0]), "=r"(r[1]) : "r"(a));
}
__device__ __forceinline__ void mma_bf16(float d[4], const uint32_t a[4], const uint32_t b[2]) {
    asm volatile(
        "mma.sync.aligned.m16n8k16.row.col.f32.bf16.bf16.f32 "
        "{%0,%1,%2,%3}, {%4,%5,%6,%7}, {%8,%9}, {%0,%1,%2,%3};"
        : "+f"(d[0]), "+f"(d[1]), "+f"(d[2]), "+f"(d[3])
        : "r"(a[0]), "r"(a[1]), "r"(a[2]), "r"(a[3]), "r"(b[0]), "r"(b[1]));
}
__device__ __forceinline__ void cpa16(uint32_t s, const void* g) {
    asm volatile("cp.async.cg.shared.global [%0], [%1], 16;" :: "r"(s), "l"(g));
}
#define CP_COMMIT() asm volatile("cp.async.commit_group;" ::: "memory")
#define CP_WAIT0()  asm volatile("cp.async.wait_group 0;" ::: "memory")

// pack two floats to bf16x2 hi + residual lo
__device__ __forceinline__ void split2(float a, float b, uint32_t& hi, uint32_t& lo) {
    __nv_bfloat162 h, l2;
    h.x = __float2bfloat16(a); h.y = __float2bfloat16(b);
    l2.x = __float2bfloat16(a - __bfloat162float(h.x));
    l2.y = __float2bfloat16(b - __bfloat162float(h.y));
    hi = *(uint32_t*)&h; lo = *(uint32_t*)&l2;
}

// ------------------------- scratch (device globals) -------------------------
__device__ float d_s1[Bb*Cc], d_b1[Bb*Cc], d_s2[Bb*Cc], d_b2[Bb*Cc];
__device__ bf16 d_thi[(size_t)Bb*Nn*Cc],  d_tlo[(size_t)Bb*Nn*Cc];   // tokens [b][tok][c]
__device__ bf16 d_whi[(size_t)QKVJ*Cc],   d_wlo[(size_t)QKVJ*Cc];    // w_qkv  [j][c]
__device__ bf16 d_wohi[(size_t)Cc*HID],   d_wolo[(size_t)Cc*HID];    // w_out  [c][j]
__device__ bf16 d_qhi[(size_t)Bb*NH*Nn*DH],   d_qlo[(size_t)Bb*NH*Nn*DH];    // [b,h][tok][d] prescaled
__device__ bf16 d_khi[(size_t)Bb*NH*Lpad*DH], d_klo[(size_t)Bb*NH*Lpad*DH];  // [b,h][tok][d]
__device__ bf16 d_vhi[(size_t)Bb*NH*DH*Lpad], d_vlo[(size_t)Bb*NH*DH*Lpad];  // [b,h][d][tok]
__device__ bf16 d_ohi[(size_t)Bb*Nn*HID], d_olo[(size_t)Bb*Nn*HID];  // attn out [b][tok][j]
__device__ float d_y[(size_t)Bb*Cc*Nn];

// ------------------------- GroupNorm stats -> affine -------------------------
__global__ void gn_stats_kernel(const float* __restrict__ src,
                                const float* __restrict__ w,
                                const float* __restrict__ bgn,
                                float* __restrict__ sout,
                                float* __restrict__ bout) {
    int b = blockIdx.x >> 5;
    int g = blockIdx.x & 31;
    const float* p = src + ((size_t)b*Cc + g*CG) * Nn;
    float sum = 0.f, sq = 0.f;
    for (int i = threadIdx.x; i < CG*Nn; i += 256) {
        float v = p[i]; sum += v; sq += v*v;
    }
    __shared__ float r0[8], r1[8];
    __shared__ float smu, srs;
    int lane = threadIdx.x & 31, wid = threadIdx.x >> 5;
#pragma unroll
    for (int off = 16; off; off >>= 1) {
        sum += __shfl_xor_sync(~0u, sum, off);
        sq  += __shfl_xor_sync(~0u, sq,  off);
    }
    if (!lane) { r0[wid] = sum; r1[wid] = sq; }
    __syncthreads();
    if (threadIdx.x == 0) {
        float s = 0.f, q = 0.f;
#pragma unroll
        for (int i = 0; i < 8; i++) { s += r0[i]; q += r1[i]; }
        float inv = 1.f / (float)(CG*Nn);
        float mu  = s * inv;
        float var = q * inv - mu*mu;
        smu = mu; srs = rsqrtf(var + 1e-5f);
    }
    __syncthreads();
    if (threadIdx.x < CG) {
        int c = g*CG + threadIdx.x;
        float ww = w[c];
        float sc = srs * ww;
        sout[b*Cc + c] = sc;
        bout[b*Cc + c] = bgn[c] - smu * sc;
    }
}

// ------------------------- prep: transpose x + GN1 affine + bf16 split -------------------------
__global__ void prep_x_kernel(const float* __restrict__ x) {
    __shared__ float t[32][33];
    int b = blockIdx.z;
    int c0 = blockIdx.y * 32;
    int t0 = blockIdx.x * 32;
    int lx = threadIdx.x & 31, ly = threadIdx.x >> 5;
#pragma unroll
    for (int i = 0; i < 4; i++) {
        int c = c0 + ly + i*8;
        float v = x[((size_t)b*Cc + c)*Nn + t0 + lx];
        t[ly + i*8][lx] = v * d_s1[b*Cc + c] + d_b1[b*Cc + c];
    }
    __syncthreads();
#pragma unroll
    for (int i = 0; i < 4; i++) {
        int tok = t0 + ly + i*8;
        int c = c0 + lx;
        float v = t[lx][ly + i*8];
        bf16 hi = __float2bfloat16(v);
        bf16 lo = __float2bfloat16(v - __bfloat162float(hi));
        size_t idx = ((size_t)b*Nn + tok)*Cc + c;
        d_thi[idx] = hi; d_tlo[idx] = lo;
    }
}

// ------------------------- prep: split both weight matrices (one launch) -------------------------
#define SPLIT1_BLOCKS ((QKVJ*Cc)/256)
__global__ void split_both_kernel(const float* __restrict__ w_qkv,
                                  const float* __restrict__ w_out) {
    int blk = blockIdx.x;
    const float* src; bf16 *hi, *lo; int i;
    if (blk < SPLIT1_BLOCKS) {
        src = w_qkv; hi = d_whi; lo = d_wlo;
        i = blk * 256 + threadIdx.x;
    } else {
        src = w_out; hi = d_wohi; lo = d_wolo;
        i = (blk - SPLIT1_BLOCKS) * 256 + threadIdx.x;
    }
    float v = src[i];
    bf16 h = __float2bfloat16(v);
    hi[i] = h;
    lo[i] = __float2bfloat16(v - __bfloat162float(h));
}

// ------------------------- memory kv prepend + zero pad (coalesced, wide grid) -------------------------
#define PADT (Lpad - Ltot)    // 124
// grid: Bb*NH*8 blocks of 256; blockIdx.x = bh*8 + part
__global__ void fill_memkv_kernel(const float* __restrict__ mem) {
    int blk = blockIdx.x;
    int bh = blk >> 3, part = blk & 7;
    int h = bh & 7, b = bh >> 3;
    int t = threadIdx.x;
    const bf16 z = __float2bfloat16(0.f);

    if (part == 0) {
        // mem kv values: 256 threads == NKV*DH
        int l = t >> 6, d = t & 63;
        float kv = mem[((size_t)h*DH + d)*NKV + l];
        float vv = mem[((size_t)(NH + h)*DH + d)*NKV + l];
        bf16 kh = __float2bfloat16(kv);
        bf16 vh = __float2bfloat16(vv);
        size_t ki = ((size_t)bh*Lpad + l)*DH + d;
        size_t vi = ((size_t)bh*DH + d)*Lpad + l;
        d_khi[ki] = kh; d_klo[ki] = __float2bfloat16(kv - __bfloat162float(kh));
        d_vhi[vi] = vh; d_vlo[vi] = __float2bfloat16(vv - __bfloat162float(vh));
    }
    // K pad rows [Ltot, Lpad) x DH, contiguous in d — 4 parts
    {
        int seg = part & 3;            // 4 segs of 31 rows
        for (int i = t; i < 31*DH; i += 256) {
            int r = seg*31 + i / DH, d = i % DH;
            size_t ki = ((size_t)bh*Lpad + Ltot + r)*DH + d;
            if (part < 4) { d_khi[ki] = z; d_klo[ki] = z; }
        }
    }
    // V pad: [d][Ltot..Lpad), contiguous in tok — 4 parts over d
    if (part >= 4) {
        int seg = part & 3;            // 16 d-rows each
        for (int i = t; i < 16*PADT; i += 256) {
            int d = seg*16 + i / PADT, off = i % PADT;
            size_t vi = ((size_t)bh*DH + d)*Lpad + Ltot + off;
            d_vhi[vi] = z; d_vlo[vi] = z;
        }
    }
}

// ------------------------- bf16x3 mma.sync mainloop (projection GEMMs) -------------------------
#define SA_HI 0u
#define SA_LO 16384u
#define SB_HI 32768u
#define SB_LO 49152u

__device__ __forceinline__ void gemm_bf16x3_acc(
    const bf16* __restrict__ Ahi, const bf16* __restrict__ Alo,
    const bf16* __restrict__ Bhi, const bf16* __restrict__ Blo,
    char* smem, float acc[4][4][4])
{
    const int tid = threadIdx.x;
    const int w = tid >> 5, l = tid & 31;
    const int mb = (w >> 2) * 64, nb = (w & 3) * 32;
    const uint32_t sbase = smem_u32_of(smem);

    const int arow = (l & 7) + ((l >> 3) & 1) * 8;
    const int acol = (l & 16) ? 16 : 0;
    const int brow = l & 7;
    const int bcol = (l & 8) ? 16 : 0;

    const bf16* srcs[4] = {Ahi, Alo, Bhi, Blo};

    for (int ch = 0; ch < 8; ch++) {
        if (ch) __syncthreads();
        int k0 = ch * 64;
#pragma unroll
        for (int tI = 0; tI < 4; tI++) {
            const char* src = (const char*)srcs[tI] + k0*2;
            uint32_t tb = tI * 16384u;
#pragma unroll
            for (int it = 0; it < 4; it++) {
                int idx = tid + it*256;
                int row = idx >> 3, u = idx & 7;
                uint4 v = *(const uint4*)(src + (size_t)row*1024 + u*16);
                uint32_t boff = (uint32_t)row*128u + (uint32_t)u*16u;
                *(uint4*)(smem + tb + SW128B(boff)) = v;
            }
        }
        __syncthreads();

#pragma unroll
        for (int ks = 0; ks < 4; ks++) {
            int kb = ks * 32;
            uint32_t ah[4][4], al[4][4];
#pragma unroll
            for (int mt = 0; mt < 4; mt++) {
                uint32_t off = SW128B((uint32_t)(mb + mt*16 + arow)*128u + kb + acol);
                ldm_x4(ah[mt], sbase + SA_HI + off);
                ldm_x4(al[mt], sbase + SA_LO + off);
            }
            uint32_t bh[4][2], bl[4][2];
#pragma unroll
            for (int nt = 0; nt < 4; nt++) {
                uint32_t off = SW128B((uint32_t)(nb + nt*8 + brow)*128u + kb + bcol);
                ldm_x2(bh[nt], sbase + SB_HI + off);
                ldm_x2(bl[nt], sbase + SB_LO + off);
            }
#pragma unroll
            for (int mt = 0; mt < 4; mt++)
#pragma unroll
                for (int nt = 0; nt < 4; nt++) {
                    mma_bf16(acc[mt][nt], ah[mt], bh[nt]);
                    mma_bf16(acc[mt][nt], al[mt], bh[nt]);
                    mma_bf16(acc[mt][nt], ah[mt], bl[nt]);
                }
        }
    }
}

// ------------------------- QKV GEMM (mma.sync bf16x3) -> bf16 hi/lo q/k/v -------------------------
__global__ __launch_bounds__(256, 1) void qkv_mma_kernel() {
    extern __shared__ __align__(16) char smem[];
    int b = blockIdx.z, m0 = blockIdx.x * 128, n0 = blockIdx.y * 128;

    float acc[4][4][4];
#pragma unroll
    for (int i = 0; i < 4; i++)
#pragma unroll
        for (int j = 0; j < 4; j++)
#pragma unroll
            for (int r = 0; r < 4; r++) acc[i][j][r] = 0.f;

    gemm_bf16x3_acc(d_thi + ((size_t)b*Nn + m0)*Cc, d_tlo + ((size_t)b*Nn + m0)*Cc,
                    d_whi + (size_t)n0*Cc,          d_wlo + (size_t)n0*Cc,
                    smem, acc);

    const int tid = threadIdx.x, w = tid >> 5, l = tid & 31;
    const int mb = (w >> 2) * 64, nb = (w & 3) * 32;
    const int trow = l >> 2, tcol = (l & 3) * 2;
    const int sec = n0 >> 9;     // 0=q 1=k 2=v
    const float mult = (sec == 0) ? SCALE : 1.f;

#pragma unroll
    for (int mt = 0; mt < 4; mt++) {
#pragma unroll
        for (int nt = 0; nt < 4; nt++) {
            int tok = m0 + mb + mt*16 + trow;
            int j   = n0 + nb + nt*8 + tcol;
            int jl  = j & 511;
            int hh  = jl >> 6, dd = jl & 63;
            int bh  = b*NH + hh;
            float* a4 = acc[mt][nt];
            if (sec == 2) {
                // V: [d][tok]
#pragma unroll
                for (int e = 0; e < 4; e++) {
                    float v = a4[e];
                    int ddx = dd + (e & 1);
                    int tk  = NKV + tok + (e >> 1)*8;
                    bf16 h = __float2bfloat16(v);
                    size_t idx = ((size_t)bh*DH + ddx)*Lpad + tk;
                    d_vhi[idx] = h;
                    d_vlo[idx] = __float2bfloat16(v - __bfloat162float(h));
                }
            } else {
                bf16* ahp; bf16* alp; size_t ridx0, ridx1;
                if (sec == 0) {
                    ahp = d_qhi; alp = d_qlo;
                    ridx0 = ((size_t)bh*Nn + tok)*DH + dd;
                    ridx1 = ((size_t)bh*Nn + tok + 8)*DH + dd;
                } else {
                    ahp = d_khi; alp = d_klo;
                    ridx0 = ((size_t)bh*Lpad + NKV + tok)*DH + dd;
                    ridx1 = ((size_t)bh*Lpad + NKV + tok + 8)*DH + dd;
                }
                uint32_t h32, l32;
                split2(a4[0]*mult, a4[1]*mult, h32, l32);
                *(uint32_t*)(ahp + ridx0) = h32;
                *(uint32_t*)(alp + ridx0) = l32;
                split2(a4[2]*mult, a4[3]*mult, h32, l32);
                *(uint32_t*)(ahp + ridx1) = h32;
                *(uint32_t*)(alp + ridx1) = l32;
            }
        }
    }
}

// ------------------------- output projection GEMM (mma.sync bf16x3) -------------------------
__global__ __launch_bounds__(256, 1) void out_mma_kernel(const float* __restrict__ bout) {
    extern __shared__ __align__(16) char smem[];
    int b = blockIdx.z, m0 = blockIdx.x * 128, n0 = blockIdx.y * 128;

    float acc[4][4][4];
#pragma unroll
    for (int i = 0; i < 4; i++)
#pragma unroll
        for (int j = 0; j < 4; j++)
#pragma unroll
            for (int r = 0; r < 4; r++) acc[i][j][r] = 0.f;

    gemm_bf16x3_acc(d_ohi + ((size_t)b*Nn + m0)*HID, d_olo + ((size_t)b*Nn + m0)*HID,
                    d_wohi + (size_t)n0*HID,         d_wolo + (size_t)n0*HID,
                    smem, acc);

    const int tid = threadIdx.x, w = tid >> 5, l = tid & 31;
    const int mb = (w >> 2) * 64, nb = (w & 3) * 32;
    const int trow = l >> 2, tcol = (l & 3) * 2;

#pragma unroll
    for (int mt = 0; mt < 4; mt++) {
#pragma unroll
        for (int nt = 0; nt < 4; nt++) {
            int tok = m0 + mb + mt*16 + trow;
            int cc  = n0 + nb + nt*8 + tcol;
            float b0 = bout[cc], b1 = bout[cc+1];
            float* a4 = acc[mt][nt];
            d_y[((size_t)b*Cc + cc)*Nn + tok]       = a4[0] + b0;
            d_y[((size_t)b*Cc + cc+1)*Nn + tok]     = a4[1] + b1;
            d_y[((size_t)b*Cc + cc)*Nn + tok + 8]   = a4[2] + b0;
            d_y[((size_t)b*Cc + cc+1)*Nn + tok + 8] = a4[3] + b1;
        }
    }
}

// ------------------------- Flash attention (mma.sync, cp.async double-buffered, x4 B-pairing) ----
// smem: buf0 [KH 0|KL 16K|VH 32K|VL 48K], buf1 [64K..128K), PH 128K (32K), PL 160K (32K),
//       QH 192K (16K), QL 208K (16K). total 224K.
#define FB(buf)  ((uint32_t)(buf)*65536u)
#define F_KH 0u
#define F_KL 16384u
#define F_VH 32768u
#define F_VL 49152u
#define F_PH 131072u
#define F_PL 163840u
#define F_QH 196608u
#define F_QL 212992u
#define FLASH_SMEM_BYTES 229376

// issue cp.async loads of K/V tile kt into buffer buf
__device__ __forceinline__ void flash_prefetch(uint32_t sb, int bh, int kt, int buf, int tid) {
    const bf16* kh_g = d_khi + ((size_t)bh*Lpad + kt*KT)*DH;
    const bf16* kl_g = d_klo + ((size_t)bh*Lpad + kt*KT)*DH;
#pragma unroll
    for (int i = 0; i < 4; i++) {
        int idx = tid + i*256;
        int row = idx >> 3, u = idx & 7;
        uint32_t so = SW128B((uint32_t)row*128u + (uint32_t)u*16u);
        cpa16(sb + FB(buf) + F_KH + so, kh_g + (size_t)row*DH + u*8);
        cpa16(sb + FB(buf) + F_KL + so, kl_g + (size_t)row*DH + u*8);
    }
    const bf16* vh_g = d_vhi + (size_t)bh*DH*Lpad + kt*KT;
    const bf16* vl_g = d_vlo + (size_t)bh*DH*Lpad + kt*KT;
#pragma unroll
    for (int i = 0; i < 4; i++) {
        int idx = tid + i*256;
        int dd = idx >> 4, c = idx & 15;
        int hf = c >> 3, u = c & 7;
        uint32_t so = (uint32_t)hf*8192u + SW128B((uint32_t)dd*128u + (uint32_t)u*16u);
        size_t g = (size_t)dd*Lpad + hf*64 + u*8;
        cpa16(sb + FB(buf) + F_VH + so, vh_g + g);
        cpa16(sb + FB(buf) + F_VL + so, vl_g + g);
    }
}

__global__ __launch_bounds__(256, 1) void flash_mma_kernel() {
    extern __shared__ __align__(16) char smem[];
    const uint32_t sb = smem_u32_of(smem);
    const int qt = blockIdx.x, h = blockIdx.y, b = blockIdx.z;
    const int bh = b*NH + h;
    const int tid = threadIdx.x, w = tid >> 5, l = tid & 31;
    const int trow = l >> 2, tcol = (l & 3) * 2;

    // ---- prologue: Q + tile0 via cp.async ----
    const bf16* qh_g = d_qhi + ((size_t)bh*Nn + qt*KT)*DH;
    const bf16* ql_g = d_qlo + ((size_t)bh*Nn + qt*KT)*DH;
#pragma unroll
    for (int i = 0; i < 4; i++) {
        int idx = tid + i*256;
        int row = idx >> 3, u = idx & 7;
        uint32_t so = SW128B((uint32_t)row*128u + (uint32_t)u*16u);
        cpa16(sb + F_QH + so, qh_g + (size_t)row*DH + u*8);
        cpa16(sb + F_QL + so, ql_g + (size_t)row*DH + u*8);
    }
    flash_prefetch(sb, bh, 0, 0, tid);
    CP_COMMIT();
    CP_WAIT0();
    __syncthreads();

    // ---- Q fragments (proven A-path; rows w*16..w*16+15) ----
    const int arow = (l & 7) + ((l >> 3) & 1) * 8;
    const int acol = (l & 16) ? 16 : 0;
    // x4 B-pairing lane map: two stacked 8-row n-tiles + both k-halves in one ldmatrix
    const int xrow = ((l >> 4) & 1) * 8 + (l & 7);
    const int xcol = ((l >> 3) & 1) * 16;
    uint32_t qfh[4][4], qfl[4][4];
#pragma unroll
    for (int ks = 0; ks < 4; ks++) {
        uint32_t off = SW128B((uint32_t)(w*16 + arow)*128u + ks*32 + acol);
        ldm_x4(qfh[ks], sb + F_QH + off);
        ldm_x4(qfl[ks], sb + F_QL + off);
    }

    float mrow[2] = {-1e30f, -1e30f};
    float lrow[2] = {0.f, 0.f};
    float oacc[8][4];
#pragma unroll
    for (int nt = 0; nt < 8; nt++)
#pragma unroll
        for (int r = 0; r < 4; r++) oacc[nt][r] = 0.f;

    for (int kt = 0; kt < NKT; kt++) {
        const int buf = kt & 1;
        if (kt + 1 < NKT) {
            flash_prefetch(sb, bh, kt + 1, buf ^ 1, tid);
            CP_COMMIT();
        }
        const uint32_t KHb = FB(buf) + F_KH, KLb = FB(buf) + F_KL;
        const uint32_t VHb = FB(buf) + F_VH, VLb = FB(buf) + F_VL;

        // ---- S = Q K^T (x4 B-pairing: one ldm_x4 covers two n-tiles) ----
        float sacc[16][4];
#pragma unroll
        for (int nt = 0; nt < 16; nt++)
#pragma unroll
            for (int r = 0; r < 4; r++) sacc[nt][r] = 0.f;

#pragma unroll
        for (int ks = 0; ks < 4; ks++) {
#pragma unroll
            for (int nt2 = 0; nt2 < 8; nt2++) {
                uint32_t off = SW128B((uint32_t)(nt2*16 + xrow)*128u + ks*32 + xcol);
                uint32_t kh4[4], kl4[4];
                ldm_x4(kh4, sb + KHb + off);
                ldm_x4(kl4, sb + KLb + off);
                mma_bf16(sacc[2*nt2],   qfh[ks], kh4);
                mma_bf16(sacc[2*nt2],   qfl[ks], kh4);
                mma_bf16(sacc[2*nt2],   qfh[ks], kl4);
                mma_bf16(sacc[2*nt2+1], qfh[ks], kh4+2);
                mma_bf16(sacc[2*nt2+1], qfl[ks], kh4+2);
                mma_bf16(sacc[2*nt2+1], qfh[ks], kl4+2);
            }
        }

        // ---- mask tail tile ----
        if (kt == NKT - 1) {
#pragma unroll
            for (int nt = 0; nt < 16; nt++) {
                int k0i = kt*KT + nt*8 + tcol;
                if (k0i >= Ltot)     { sacc[nt][0] = -1e30f; sacc[nt][2] = -1e30f; }
                if (k0i + 1 >= Ltot) { sacc[nt][1] = -1e30f; sacc[nt][3] = -1e30f; }
            }
        }

        // ---- online softmax (rows trow, trow+8; quad-shfl reduce) ----
#pragma unroll
        for (int r = 0; r < 2; r++) {
            int ro = 2*r;
            float rm = -1e30f;
#pragma unroll
            for (int nt = 0; nt < 16; nt++)
                rm = fmaxf(rm, fmaxf(sacc[nt][ro], sacc[nt][ro+1]));
            rm = fmaxf(rm, __shfl_xor_sync(~0u, rm, 1, 4));
            rm = fmaxf(rm, __shfl_xor_sync(~0u, rm, 2, 4));
            float mn = fmaxf(mrow[r], rm);
            float alpha = __expf(mrow[r] - mn);
            mrow[r] = mn;
            float rs = 0.f;
#pragma unroll
            for (int nt = 0; nt < 16; nt++) {
                float p0 = __expf(sacc[nt][ro]   - mn);
                float p1 = __expf(sacc[nt][ro+1] - mn);
                sacc[nt][ro] = p0; sacc[nt][ro+1] = p1;
                rs += p0 + p1;
            }
            rs += __shfl_xor_sync(~0u, rs, 1, 4);
            rs += __shfl_xor_sync(~0u, rs, 2, 4);
            lrow[r] = lrow[r]*alpha + rs;
#pragma unroll
            for (int nt = 0; nt < 8; nt++) {
                oacc[nt][ro] *= alpha; oacc[nt][ro+1] *= alpha;
            }
        }

        // ---- write P hi/lo to smem [2 half][128 q][64 tok] (warp-private rows) ----
#pragma unroll
        for (int nt = 0; nt < 16; nt++) {
            int col = nt*8 + tcol;
            uint32_t hf = (uint32_t)(col >> 6) * 16384u;
            uint32_t bc = (uint32_t)(col & 63) * 2u;
            uint32_t h32, l32;
            split2(sacc[nt][0], sacc[nt][1], h32, l32);
            uint32_t o0 = hf + SW128B((uint32_t)(w*16 + trow)*128u + bc);
            *(uint32_t*)(smem + F_PH + o0) = h32;
            *(uint32_t*)(smem + F_PL + o0) = l32;
            split2(sacc[nt][2], sacc[nt][3], h32, l32);
            uint32_t o1 = hf + SW128B((uint32_t)(w*16 + trow + 8)*128u + bc);
            *(uint32_t*)(smem + F_PH + o1) = h32;
            *(uint32_t*)(smem + F_PL + o1) = l32;
        }
        __syncwarp();

        // ---- O += P V (A-path for P; x4 B-pairing for V) ----
#pragma unroll
        for (int ks2 = 0; ks2 < 8; ks2++) {
            uint32_t hfA = (uint32_t)(ks2 >> 2) * 16384u;
            uint32_t hfB = (uint32_t)(ks2 >> 2) * 8192u;
            uint32_t kb  = (uint32_t)(ks2 & 3) * 32u;
            uint32_t pfh[4], pfl[4];
            uint32_t offA = hfA + SW128B((uint32_t)(w*16 + arow)*128u + kb + acol);
            ldm_x4(pfh, sb + F_PH + offA);
            ldm_x4(pfl, sb + F_PL + offA);
#pragma unroll
            for (int nt2 = 0; nt2 < 4; nt2++) {
                uint32_t offB = hfB + SW128B((uint32_t)(nt2*16 + xrow)*128u + kb + xcol);
                uint32_t vh4[4], vl4[4];
                ldm_x4(vh4, sb + VHb + offB);
                ldm_x4(vl4, sb + VLb + offB);
                mma_bf16(oacc[2*nt2],   pfh, vh4);
                mma_bf16(oacc[2*nt2],   pfl, vh4);
                mma_bf16(oacc[2*nt2],   pfh, vl4);
                mma_bf16(oacc[2*nt2+1], pfh, vh4+2);
                mma_bf16(oacc[2*nt2+1], pfl, vh4+2);
                mma_bf16(oacc[2*nt2+1], pfh, vl4+2);
            }
        }

        if (kt + 1 < NKT) {
            CP_WAIT0();        // next buffer landed
            __syncthreads();   // all warps done reading current buffer + P
        }
    }

    // ---- epilogue: O/l -> bf16 hi/lo [tok][HID] ----
#pragma unroll
    for (int r = 0; r < 2; r++) {
        float inv = 1.f / lrow[r];
        int tok = qt*KT + w*16 + trow + r*8;
        size_t rowb = (size_t)(b*Nn + tok)*HID + h*DH;
#pragma unroll
        for (int nt = 0; nt < 8; nt++) {
            uint32_t h32, l32;
            split2(oacc[nt][2*r]*inv, oacc[nt][2*r+1]*inv, h32, l32);
            int col = nt*8 + tcol;
            *(uint32_t*)(d_ohi + rowb + col) = h32;
            *(uint32_t*)(d_olo + rowb + col) = l32;
        }
    }
}

// ------------------------- GN2 apply -> final output -------------------------
__global__ void gn_apply_kernel(float* __restrict__ out) {
    int f = blockIdx.x * 256 + threadIdx.x;
    float4 v = ((const float4*)d_y)[f];
    int bc = f / (Nn/4);
    float s = d_s2[bc], bb = d_b2[bc];
    float4 r;
    r.x = v.x*s + bb; r.y = v.y*s + bb; r.z = v.z*s + bb; r.w = v.w*s + bb;
    ((float4*)out)[f] = r;
}

// ------------------------- launch -------------------------
extern "C" void kernel_launch(void* const* d_in, const int* in_sizes, int n_in,
                              void* d_out, int out_size) {
    const float* x     = (const float*)d_in[0];
    const float* gn1_w = (const float*)d_in[1];
    const float* gn1_b = (const float*)d_in[2];
    const float* w_qkv = (const float*)d_in[3];
    const float* memkv = (const float*)d_in[4];
    const float* w_out = (const float*)d_in[5];
    const float* b_out = (const float*)d_in[6];
    const float* gn2_w = (const float*)d_in[7];
    const float* gn2_b = (const float*)d_in[8];
    float* out = (float*)d_out;

    const int GEMM_SMEM = 65536;

    static bool attr_set = false;
    if (!attr_set) {
        cudaFuncSetAttribute(flash_mma_kernel, cudaFuncAttributeMaxDynamicSharedMemorySize, FLASH_SMEM_BYTES);
        cudaFuncSetAttribute(qkv_mma_kernel,   cudaFuncAttributeMaxDynamicSharedMemorySize, GEMM_SMEM);
        cudaFuncSetAttribute(out_mma_kernel,   cudaFuncAttributeMaxDynamicSharedMemorySize, GEMM_SMEM);
        attr_set = true;
    }

    float *p_s1, *p_b1, *p_s2, *p_b2, *p_y;
    cudaGetSymbolAddress((void**)&p_s1, d_s1);
    cudaGetSymbolAddress((void**)&p_b1, d_b1);
    cudaGetSymbolAddress((void**)&p_s2, d_s2);
    cudaGetSymbolAddress((void**)&p_b2, d_b2);
    cudaGetSymbolAddress((void**)&p_y, d_y);

    gn_stats_kernel<<<Bb*Gg, 256>>>(x, gn1_w, gn1_b, p_s1, p_b1);
    prep_x_kernel<<<dim3(Nn/32, Cc/32, Bb), 256>>>(x);
    split_both_kernel<<<SPLIT1_BLOCKS + (Cc*HID)/256, 256>>>(w_qkv, w_out);
    fill_memkv_kernel<<<Bb*NH*8, 256>>>(memkv);
    qkv_mma_kernel<<<dim3(Nn/128, QKVJ/128, Bb), 256, GEMM_SMEM>>>();
    flash_mma_kernel<<<dim3(Nn/KT, NH, Bb), 256, FLASH_SMEM_BYTES>>>();
    out_mma_kernel<<<dim3(Nn/128, HID/128, Bb), 256, GEMM_SMEM>>>(b_out);
    gn_stats_kernel<<<Bb*Gg, 256>>>(p_y, gn2_w, gn2_b, p_s2, p_b2);
    gn_apply_kernel<<<(Bb*Cc*Nn/4)/256, 256>>>(out);
}